// round 9
// baseline (speedup 1.0000x reference)
#include <cuda_runtime.h>
#include <cuda_bf16.h>
#include <math.h>
#include <stdint.h>

#define NN   262144
#define EE   2097152
#define HID  200
#define MT   128                 // rows per CTA
#define CAC  232                 // A smem cols (k padded; stride 464B conflict-free)
#define NCHK 7                   // k chunks of 32 (224 >= 200, zero padded)
#define NG   (6 * NCHK)          // 42 global chunks across layers 1..6
#define BNC  216                 // B smem cols (n padded; stride 432B conflict-free)
#define SA_PLANE (MT * CAC * 2)          // 59392 B per A plane
#define SM_A_HI  0
#define SM_A_LO  SA_PLANE
#define SM_B     (2 * SA_PLANE)          // 118784
#define BPLANE   (32 * BNC * 2)          // 13824 B
#define BUFSZ    (2 * BPLANE)            // 27648 B (hi+lo)
#define SMEM_BYTES (SM_B + 3 * BUFSZ)    // 201728
#define THREADS  256

// ------------------------- device globals (scratch) -------------------------
__device__ float g_deg[NN];
__device__ float g_inv[NN];
__device__ float g_agg[NN];
__device__ int   g_is64;
// weights pre-split bf16 hi/lo: [layer 1..6][chunk][plane][k32][BNC]
__device__ __align__(16) __nv_bfloat16 g_wtB[6][NCHK][2][32][BNC];

struct Params {
    const float* W[8];
    const float* b[8];
};

// ------------------------------- PTX helpers --------------------------------
__device__ __forceinline__ uint32_t smem_u32(const void* p) {
    uint32_t a;
    asm("{ .reg .u64 t; cvta.to.shared.u64 t, %1; cvt.u32.u64 %0, t; }" : "=r"(a) : "l"(p));
    return a;
}
__device__ __forceinline__ void cp16(uint32_t sdst, const void* gsrc) {
    asm volatile("cp.async.cg.shared.global [%0], [%1], 16;" :: "r"(sdst), "l"(gsrc));
}
#define CP_COMMIT() asm volatile("cp.async.commit_group;")
#define CP_WAIT1()  asm volatile("cp.async.wait_group 1;")
#define CP_WAIT0()  asm volatile("cp.async.wait_group 0;")

__device__ __forceinline__ void ldsm_x4(uint32_t* r, uint32_t addr) {
    asm volatile("ldmatrix.sync.aligned.m8n8.x4.shared.b16 {%0,%1,%2,%3}, [%4];"
                 : "=r"(r[0]), "=r"(r[1]), "=r"(r[2]), "=r"(r[3]) : "r"(addr));
}
__device__ __forceinline__ void ldsm_x4t(uint32_t* r, uint32_t addr) {
    asm volatile("ldmatrix.sync.aligned.m8n8.x4.trans.shared.b16 {%0,%1,%2,%3}, [%4];"
                 : "=r"(r[0]), "=r"(r[1]), "=r"(r[2]), "=r"(r[3]) : "r"(addr));
}
__device__ __forceinline__ void ldsm_x2t(uint32_t* r, uint32_t addr) {
    asm volatile("ldmatrix.sync.aligned.m8n8.x2.trans.shared.b16 {%0,%1}, [%2];"
                 : "=r"(r[0]), "=r"(r[1]) : "r"(addr));
}
__device__ __forceinline__ void mma16816(float* d, const uint32_t* a, uint32_t b0, uint32_t b1) {
    asm volatile(
        "mma.sync.aligned.m16n8k16.row.col.f32.bf16.bf16.f32 "
        "{%0,%1,%2,%3}, {%4,%5,%6,%7}, {%8,%9}, {%0,%1,%2,%3};"
        : "+f"(d[0]), "+f"(d[1]), "+f"(d[2]), "+f"(d[3])
        : "r"(a[0]), "r"(a[1]), "r"(a[2]), "r"(a[3]), "r"(b0), "r"(b1));
}

// ------------------------- edge aggregation kernels -------------------------
__global__ void detect_kernel(const int* __restrict__ ei32) {
    if (blockIdx.x == 0 && threadIdx.x == 0) {
        int orv = 0;
        for (int i = 1; i < 128; i += 2) orv |= ei32[i];
        g_is64 = (orv == 0) ? 1 : 0;
    }
}
__device__ __forceinline__ int load_idx(const void* ei, long long pos, int is64) {
    if (is64) return (int)((const long long*)ei)[pos];
    return ((const int*)ei)[pos];
}
__global__ void zero_deg_kernel() {
    int i = blockIdx.x * blockDim.x + threadIdx.x;
    if (i < NN) g_deg[i] = 0.0f;
}
__global__ void deg_kernel(const void* __restrict__ ei) {
    const int is64 = g_is64;
    long long stride = (long long)gridDim.x * blockDim.x;
    for (long long e = (long long)blockIdx.x * blockDim.x + threadIdx.x; e < EE; e += stride) {
        int d = load_idx(ei, (long long)EE + e, is64);
        atomicAdd(&g_deg[d], 1.0f);
    }
}
__global__ void inv_init_kernel(const float* __restrict__ x) {
    int i = blockIdx.x * blockDim.x + threadIdx.x;
    if (i < NN) {
        float inv = rsqrtf(g_deg[i] + 1.0f);
        g_inv[i] = inv;
        g_agg[i] = x[i] * inv * inv;
    }
}
__global__ void edge_agg_kernel(const float* __restrict__ x, const void* __restrict__ ei) {
    const int is64 = g_is64;
    long long stride = (long long)gridDim.x * blockDim.x;
    for (long long e = (long long)blockIdx.x * blockDim.x + threadIdx.x; e < EE; e += stride) {
        int s = load_idx(ei, e, is64);
        int d = load_idx(ei, (long long)EE + e, is64);
        atomicAdd(&g_agg[d], x[s] * g_inv[s] * g_inv[d]);
    }
}

// ------------------- weight prep: fp32 -> bf16 hi/lo planes -----------------
__global__ void prep_w_kernel(Params p) {
    int idx = blockIdx.x * blockDim.x + threadIdx.x;
    const int total = 6 * NCHK * 32 * BNC;
    if (idx >= total) return;
    int n = idx % BNC;
    int k = (idx / BNC) % 32;
    int c = (idx / (BNC * 32)) % NCHK;
    int l = idx / (BNC * 32 * NCHK);
    int kg = c * 32 + k;
    float v = 0.0f;
    if (kg < HID && n < HID) v = p.W[l + 1][kg * HID + n];
    __nv_bfloat16 hi = __float2bfloat16(v);
    __nv_bfloat16 lo = __float2bfloat16(v - __bfloat162float(hi));
    g_wtB[l][c][0][k][n] = hi;
    g_wtB[l][c][1][k][n] = lo;
}

// ------------------------------ fused MLP kernel ----------------------------
__device__ __forceinline__ void split_store(char* sm, int r, int j, float v0, float v1) {
    __nv_bfloat16 h0 = __float2bfloat16(v0), h1 = __float2bfloat16(v1);
    __nv_bfloat16 l0 = __float2bfloat16(v0 - __bfloat162float(h0));
    __nv_bfloat16 l1 = __float2bfloat16(v1 - __bfloat162float(h1));
    uint32_t hp = (uint32_t)__bfloat16_as_ushort(h0) | ((uint32_t)__bfloat16_as_ushort(h1) << 16);
    uint32_t lp = (uint32_t)__bfloat16_as_ushort(l0) | ((uint32_t)__bfloat16_as_ushort(l1) << 16);
    *(uint32_t*)(sm + SM_A_HI + r * (CAC * 2) + j * 2) = hp;
    *(uint32_t*)(sm + SM_A_LO + r * (CAC * 2) + j * 2) = lp;
}

__global__ void __launch_bounds__(THREADS, 1) mlp_kernel(Params p, float* __restrict__ out) {
    extern __shared__ char sm[];
    const uint32_t sbase = smem_u32(sm);
    const int tid  = threadIdx.x;
    const int wid  = tid >> 5;
    const int lane = tid & 31;
    const int wr   = wid & 3;       // row group: rows 32*wr..+31 (two m16 subtiles)
    const int wc   = wid >> 2;      // col half: cols 104*wc..+103
    const int row0 = blockIdx.x * MT;

    // ldmatrix lane address components
    const int mrow  = (lane & 7) + 8 * ((lane >> 3) & 1);
    const int koff8 = 8 * (lane >> 4);
    const uint32_t aHi0 = sbase + SM_A_HI + (wr * 32 + mrow) * (CAC * 2) + koff8 * 2;
    const uint32_t aLo0 = sbase + SM_A_LO + (wr * 32 + mrow) * (CAC * 2) + koff8 * 2;
    const uint32_t aHi1 = aHi0 + 16 * (CAC * 2);
    const uint32_t aLo1 = aLo0 + 16 * (CAC * 2);
    const uint32_t bOff = (uint32_t)(mrow * (BNC * 2) + koff8 * 2);

    // issue first two weight chunks (overlaps with layer-0 gather below)
    const char* wflat = (const char*)&g_wtB[0][0][0][0][0];
    {
        for (int i = tid * 16; i < BUFSZ; i += THREADS * 16)
            cp16(sbase + SM_B + i, wflat + i);
        CP_COMMIT();
        for (int i = tid * 16; i < BUFSZ; i += THREADS * 16)
            cp16(sbase + SM_B + BUFSZ + i, wflat + BUFSZ + i);
        CP_COMMIT();
    }

    // ---- layer 0: A = relu(agg * W0 + b0) -> bf16 hi/lo, zero padding ----
    {
        const float* W0 = p.W[0];
        const float* b0 = p.b[0];
        for (int idx = tid; idx < MT * (CAC / 2); idx += THREADS) {
            int r = idx / (CAC / 2);
            int j = (idx - r * (CAC / 2)) * 2;
            float agg = g_agg[row0 + r];
            float v0 = (j < HID)     ? fmaxf(fmaf(agg, W0[j],     b0[j]),     0.0f) : 0.0f;
            float v1 = (j + 1 < HID) ? fmaxf(fmaf(agg, W0[j + 1], b0[j + 1]), 0.0f) : 0.0f;
            split_store(sm, r, j, v0, v1);
        }
    }
    __syncthreads();

    int g = 0;   // global chunk counter (uniform across threads)

    for (int l = 1; l <= 6; ++l) {
        float acc[2][13][4];
        #pragma unroll
        for (int s = 0; s < 2; ++s)
            #pragma unroll
            for (int t = 0; t < 13; ++t)
                #pragma unroll
                for (int q = 0; q < 4; ++q) acc[s][t][q] = 0.0f;

        for (int c = 0; c < NCHK; ++c, ++g) {
            if (g + 2 < NG) { CP_WAIT1(); } else { CP_WAIT0(); }
            __syncthreads();          // chunk g visible; prior reads of ring slot done
            if (g + 2 < NG) {         // stage chunk g+2 into ring slot (g+2)%3
                const char* src = wflat + (size_t)(g + 2) * BUFSZ;
                uint32_t dst = sbase + SM_B + ((g + 2) % 3) * BUFSZ;
                for (int i = tid * 16; i < BUFSZ; i += THREADS * 16)
                    cp16(dst + i, src + i);
                CP_COMMIT();
            }

            const uint32_t curB = sbase + SM_B + (g % 3) * BUFSZ;
            #pragma unroll
            for (int ks = 0; ks < 2; ++ks) {
                const int kb = c * 32 + ks * 16;
                uint32_t ah[2][4], al[2][4];
                ldsm_x4(ah[0], aHi0 + kb * 2);
                ldsm_x4(ah[1], aHi1 + kb * 2);
                ldsm_x4(al[0], aLo0 + kb * 2);
                ldsm_x4(al[1], aLo1 + kb * 2);
                const uint32_t bk = curB + bOff + ks * 16 * (BNC * 2);
                #pragma unroll
                for (int pr = 0; pr < 6; ++pr) {
                    const int nc = wc * 104 + pr * 16;
                    uint32_t bh[4], bl[4];
                    ldsm_x4t(bh, bk + nc * 2);
                    ldsm_x4t(bl, bk + BPLANE + nc * 2);
                    #pragma unroll
                    for (int s = 0; s < 2; ++s) {
                        mma16816(acc[s][2 * pr],     ah[s], bh[0], bh[1]);
                        mma16816(acc[s][2 * pr],     ah[s], bl[0], bl[1]);
                        mma16816(acc[s][2 * pr],     al[s], bh[0], bh[1]);
                        mma16816(acc[s][2 * pr + 1], ah[s], bh[2], bh[3]);
                        mma16816(acc[s][2 * pr + 1], ah[s], bl[2], bl[3]);
                        mma16816(acc[s][2 * pr + 1], al[s], bh[2], bh[3]);
                    }
                }
                // tile 12 (cols 96..103): s = wc subtile only -> balanced 75/75
                {
                    uint32_t bh2[2], bl2[2];
                    ldsm_x2t(bh2, bk + 96 * 2);
                    ldsm_x2t(bl2, bk + BPLANE + 96 * 2);
                    mma16816(acc[wc][12], ah[wc], bh2[0], bh2[1]);
                    mma16816(acc[wc][12], ah[wc], bl2[0], bl2[1]);
                    mma16816(acc[wc][12], al[wc], bh2[0], bh2[1]);
                }
            }
        }

        __syncthreads();   // all A reads of this layer done before overwrite

        if (l < 6) {
            // epilogue: bias + relu + hi/lo split back into A
            const float* bias = p.b[l];
            #pragma unroll
            for (int s = 0; s < 2; ++s) {
                const int r0 = wr * 32 + s * 16 + (lane >> 2);
                const int r1 = r0 + 8;
                #pragma unroll
                for (int t = 0; t < 12; ++t) {   // j, j+1 always < 200
                    int j = wc * 104 + t * 8 + 2 * (lane & 3);
                    float bj0 = bias[j], bj1 = bias[j + 1];
                    split_store(sm, r0, j, fmaxf(acc[s][t][0] + bj0, 0.0f),
                                            fmaxf(acc[s][t][1] + bj1, 0.0f));
                    split_store(sm, r1, j, fmaxf(acc[s][t][2] + bj0, 0.0f),
                                            fmaxf(acc[s][t][3] + bj1, 0.0f));
                }
            }
            {   // tile 12: rows of s = wc subtile, cols 96..103
                const int r0 = wr * 32 + wc * 16 + (lane >> 2);
                const int r1 = r0 + 8;
                int j = 96 + 2 * (lane & 3);
                float bj0 = bias[j], bj1 = bias[j + 1];
                split_store(sm, r0, j, fmaxf(acc[wc][12][0] + bj0, 0.0f),
                                        fmaxf(acc[wc][12][1] + bj1, 0.0f));
                split_store(sm, r1, j, fmaxf(acc[wc][12][2] + bj0, 0.0f),
                                        fmaxf(acc[wc][12][3] + bj1, 0.0f));
            }
            // next layer's first chunk-iteration syncthreads publishes A
        } else {
            // final: relu(acc + b6) dot W7 -> reduce -> sigmoid
            const float* bias = p.b[6];
            const float* W7   = p.W[7];
            float* red = (float*)(sm + SM_B);
            #pragma unroll
            for (int s = 0; s < 2; ++s) {
                const int r0 = wr * 32 + s * 16 + (lane >> 2);
                const int r1 = r0 + 8;
                float p0 = 0.0f, p1 = 0.0f;
                #pragma unroll
                for (int t = 0; t < 12; ++t) {
                    int j = wc * 104 + t * 8 + 2 * (lane & 3);
                    float bj0 = bias[j], w0 = W7[j];
                    float bj1 = bias[j + 1], w1 = W7[j + 1];
                    p0 = fmaf(fmaxf(acc[s][t][0] + bj0, 0.0f), w0, p0);
                    p0 = fmaf(fmaxf(acc[s][t][1] + bj1, 0.0f), w1, p0);
                    p1 = fmaf(fmaxf(acc[s][t][2] + bj0, 0.0f), w0, p1);
                    p1 = fmaf(fmaxf(acc[s][t][3] + bj1, 0.0f), w1, p1);
                }
                if (s == wc) {   // tile 12 belongs to these rows
                    int j = 96 + 2 * (lane & 3);
                    float bj0 = bias[j], w0 = W7[j];
                    float bj1 = bias[j + 1], w1 = W7[j + 1];
                    p0 = fmaf(fmaxf(acc[wc][12][0] + bj0, 0.0f), w0, p0);
                    p0 = fmaf(fmaxf(acc[wc][12][1] + bj1, 0.0f), w1, p0);
                    p1 = fmaf(fmaxf(acc[wc][12][2] + bj0, 0.0f), w0, p1);
                    p1 = fmaf(fmaxf(acc[wc][12][3] + bj1, 0.0f), w1, p1);
                }
                p0 += __shfl_xor_sync(0xffffffff, p0, 1);
                p0 += __shfl_xor_sync(0xffffffff, p0, 2);
                p1 += __shfl_xor_sync(0xffffffff, p1, 1);
                p1 += __shfl_xor_sync(0xffffffff, p1, 2);
                if ((lane & 3) == 0) {
                    red[r0 * 2 + wc] = p0;
                    red[r1 * 2 + wc] = p1;
                }
            }
            __syncthreads();
            if (tid < MT) {
                float s = red[tid * 2] + red[tid * 2 + 1] + p.b[7][0];
                out[row0 + tid] = 1.0f / (1.0f + expf(-s));
            }
        }
    }
}

// ---------------------------------------------------------------------------
extern "C" void kernel_launch(void* const* d_in, const int* in_sizes, int n_in,
                              void* d_out, int out_size) {
    const float* x  = (const float*)d_in[0];
    const void*  ei = d_in[1];
    Params p;
    for (int i = 0; i < 8; ++i) {
        p.W[i] = (const float*)d_in[2 + 2 * i];
        p.b[i] = (const float*)d_in[3 + 2 * i];
    }
    float* out = (float*)d_out;

    cudaFuncSetAttribute(mlp_kernel, cudaFuncAttributeMaxDynamicSharedMemorySize, SMEM_BYTES);

    detect_kernel<<<1, 32>>>((const int*)ei);
    prep_w_kernel<<<(6 * NCHK * 32 * BNC + 255) / 256, 256>>>(p);
    zero_deg_kernel<<<NN / 256, 256>>>();
    deg_kernel<<<2048, 256>>>(ei);
    inv_init_kernel<<<NN / 256, 256>>>(x);
    edge_agg_kernel<<<2048, 256>>>(x, ei);
    mlp_kernel<<<NN / MT, THREADS, SMEM_BYTES>>>(p, out);
}

// round 10
// speedup vs baseline: 1.5544x; 1.5544x over previous
#include <cuda_runtime.h>
#include <cuda_bf16.h>
#include <math.h>
#include <stdint.h>

#define NN   262144
#define EE   2097152
#define HID  200
#define MT   128                 // rows per CTA
#define CAC  232                 // A smem cols (k padded; stride 464B conflict-free)
#define NCHK 7                   // k chunks of 32 (224 >= 200, zero padded)
#define NG   (6 * NCHK)          // 42 global chunks across layers 1..6
#define BNC  216                 // B smem cols (n padded; stride 432B conflict-free)
#define SA_PLANE (MT * CAC * 2)          // 59392 B per A plane
#define SM_A_HI  0
#define SM_A_LO  SA_PLANE
#define SM_B     (2 * SA_PLANE)          // 118784
#define BPLANE   (32 * BNC * 2)          // 13824 B
#define BUFSZ    (2 * BPLANE)            // 27648 B (hi+lo)
#define SMEM_BYTES (SM_B + 2 * BUFSZ)    // 174080
#define THREADS  256

// ------------------------- device globals (scratch) -------------------------
__device__ float g_deg[NN];
__device__ float g_inv[NN];
__device__ float g_agg[NN];
__device__ int   g_is64;
// weights pre-split bf16 hi/lo: [layer 1..6][chunk][plane][k32][BNC]
__device__ __align__(16) __nv_bfloat16 g_wtB[6][NCHK][2][32][BNC];

struct Params {
    const float* W[8];
    const float* b[8];
};

// ------------------------------- PTX helpers --------------------------------
__device__ __forceinline__ uint32_t smem_u32(const void* p) {
    uint32_t a;
    asm("{ .reg .u64 t; cvta.to.shared.u64 t, %1; cvt.u32.u64 %0, t; }" : "=r"(a) : "l"(p));
    return a;
}
__device__ __forceinline__ void cp16(uint32_t sdst, const void* gsrc) {
    asm volatile("cp.async.cg.shared.global [%0], [%1], 16;" :: "r"(sdst), "l"(gsrc));
}
#define CP_COMMIT() asm volatile("cp.async.commit_group;")
#define CP_WAIT1()  asm volatile("cp.async.wait_group 1;")
#define CP_WAIT0()  asm volatile("cp.async.wait_group 0;")

__device__ __forceinline__ void ldsm_x4(uint32_t* r, uint32_t addr) {
    asm volatile("ldmatrix.sync.aligned.m8n8.x4.shared.b16 {%0,%1,%2,%3}, [%4];"
                 : "=r"(r[0]), "=r"(r[1]), "=r"(r[2]), "=r"(r[3]) : "r"(addr));
}
__device__ __forceinline__ void ldsm_x4t(uint32_t* r, uint32_t addr) {
    asm volatile("ldmatrix.sync.aligned.m8n8.x4.trans.shared.b16 {%0,%1,%2,%3}, [%4];"
                 : "=r"(r[0]), "=r"(r[1]), "=r"(r[2]), "=r"(r[3]) : "r"(addr));
}
__device__ __forceinline__ void ldsm_x2t(uint32_t* r, uint32_t addr) {
    asm volatile("ldmatrix.sync.aligned.m8n8.x2.trans.shared.b16 {%0,%1}, [%2];"
                 : "=r"(r[0]), "=r"(r[1]) : "r"(addr));
}
__device__ __forceinline__ void mma16816(float* d, const uint32_t* a, uint32_t b0, uint32_t b1) {
    asm volatile(
        "mma.sync.aligned.m16n8k16.row.col.f32.bf16.bf16.f32 "
        "{%0,%1,%2,%3}, {%4,%5,%6,%7}, {%8,%9}, {%0,%1,%2,%3};"
        : "+f"(d[0]), "+f"(d[1]), "+f"(d[2]), "+f"(d[3])
        : "r"(a[0]), "r"(a[1]), "r"(a[2]), "r"(a[3]), "r"(b0), "r"(b1));
}

// ------------------------- edge aggregation kernels -------------------------
__global__ void detect_kernel(const int* __restrict__ ei32) {
    if (blockIdx.x == 0 && threadIdx.x == 0) {
        int orv = 0;
        for (int i = 1; i < 128; i += 2) orv |= ei32[i];
        g_is64 = (orv == 0) ? 1 : 0;
    }
}
__device__ __forceinline__ int load_idx(const void* ei, long long pos, int is64) {
    if (is64) return (int)((const long long*)ei)[pos];
    return ((const int*)ei)[pos];
}
__global__ void zero_deg_kernel() {
    int i = blockIdx.x * blockDim.x + threadIdx.x;
    if (i < NN) g_deg[i] = 0.0f;
}
__global__ void deg_kernel(const void* __restrict__ ei) {
    const int is64 = g_is64;
    long long stride = (long long)gridDim.x * blockDim.x;
    for (long long e = (long long)blockIdx.x * blockDim.x + threadIdx.x; e < EE; e += stride) {
        int d = load_idx(ei, (long long)EE + e, is64);
        atomicAdd(&g_deg[d], 1.0f);
    }
}
__global__ void inv_init_kernel(const float* __restrict__ x) {
    int i = blockIdx.x * blockDim.x + threadIdx.x;
    if (i < NN) {
        float inv = rsqrtf(g_deg[i] + 1.0f);
        g_inv[i] = inv;
        g_agg[i] = x[i] * inv * inv;
    }
}
__global__ void edge_agg_kernel(const float* __restrict__ x, const void* __restrict__ ei) {
    const int is64 = g_is64;
    long long stride = (long long)gridDim.x * blockDim.x;
    for (long long e = (long long)blockIdx.x * blockDim.x + threadIdx.x; e < EE; e += stride) {
        int s = load_idx(ei, e, is64);
        int d = load_idx(ei, (long long)EE + e, is64);
        atomicAdd(&g_agg[d], x[s] * g_inv[s] * g_inv[d]);
    }
}

// ------------------- weight prep: fp32 -> bf16 hi/lo planes -----------------
__global__ void prep_w_kernel(Params p) {
    int idx = blockIdx.x * blockDim.x + threadIdx.x;
    const int total = 6 * NCHK * 32 * BNC;
    if (idx >= total) return;
    int n = idx % BNC;
    int k = (idx / BNC) % 32;
    int c = (idx / (BNC * 32)) % NCHK;
    int l = idx / (BNC * 32 * NCHK);
    int kg = c * 32 + k;
    float v = 0.0f;
    if (kg < HID && n < HID) v = p.W[l + 1][kg * HID + n];
    __nv_bfloat16 hi = __float2bfloat16(v);
    __nv_bfloat16 lo = __float2bfloat16(v - __bfloat162float(hi));
    g_wtB[l][c][0][k][n] = hi;
    g_wtB[l][c][1][k][n] = lo;
}

// ------------------------------ fused MLP kernel ----------------------------
__device__ __forceinline__ void split_store(char* sm, int r, int j, float v0, float v1) {
    __nv_bfloat16 h0 = __float2bfloat16(v0), h1 = __float2bfloat16(v1);
    __nv_bfloat16 l0 = __float2bfloat16(v0 - __bfloat162float(h0));
    __nv_bfloat16 l1 = __float2bfloat16(v1 - __bfloat162float(h1));
    uint32_t hp = (uint32_t)__bfloat16_as_ushort(h0) | ((uint32_t)__bfloat16_as_ushort(h1) << 16);
    uint32_t lp = (uint32_t)__bfloat16_as_ushort(l0) | ((uint32_t)__bfloat16_as_ushort(l1) << 16);
    *(uint32_t*)(sm + SM_A_HI + r * (CAC * 2) + j * 2) = hp;
    *(uint32_t*)(sm + SM_A_LO + r * (CAC * 2) + j * 2) = lp;
}

__global__ void __launch_bounds__(THREADS, 1) mlp_kernel(Params p, float* __restrict__ out) {
    extern __shared__ char sm[];
    const uint32_t sbase = smem_u32(sm);
    const int tid  = threadIdx.x;
    const int wid  = tid >> 5;
    const int lane = tid & 31;
    const int wr   = wid & 3;       // row group: rows 32*wr..+31 (two m16 subtiles)
    const int wc   = wid >> 2;      // col half: cols 104*wc..+103
    const int row0 = blockIdx.x * MT;

    // ldmatrix lane address components
    const int mrow  = (lane & 7) + 8 * ((lane >> 3) & 1);
    const int koff8 = 8 * (lane >> 4);
    const uint32_t aHi0 = sbase + SM_A_HI + (wr * 32 + mrow) * (CAC * 2) + koff8 * 2;
    const uint32_t aLo0 = sbase + SM_A_LO + (wr * 32 + mrow) * (CAC * 2) + koff8 * 2;
    const uint32_t aHi1 = aHi0 + 16 * (CAC * 2);
    const uint32_t aLo1 = aLo0 + 16 * (CAC * 2);
    const uint32_t bOff = (uint32_t)(mrow * (BNC * 2) + koff8 * 2);

    const char* wflat = (const char*)&g_wtB[0][0][0][0][0];

    // stage global chunk 0 into buffer 0 (overlaps with layer-0 gather below)
    for (int i = tid * 16; i < BUFSZ; i += THREADS * 16)
        cp16(sbase + SM_B + i, wflat + i);
    CP_COMMIT();

    // ---- layer 0: A = relu(agg * W0 + b0) -> bf16 hi/lo, zero padding ----
    {
        const float* W0 = p.W[0];
        const float* b0 = p.b[0];
        for (int idx = tid; idx < MT * (CAC / 2); idx += THREADS) {
            int r = idx / (CAC / 2);
            int j = (idx - r * (CAC / 2)) * 2;
            float agg = g_agg[row0 + r];
            float v0 = (j < HID)     ? fmaxf(fmaf(agg, W0[j],     b0[j]),     0.0f) : 0.0f;
            float v1 = (j + 1 < HID) ? fmaxf(fmaf(agg, W0[j + 1], b0[j + 1]), 0.0f) : 0.0f;
            split_store(sm, r, j, v0, v1);
        }
    }
    __syncthreads();

    for (int l = 1; l <= 6; ++l) {
        float acc[2][13][4];
        #pragma unroll
        for (int s = 0; s < 2; ++s)
            #pragma unroll
            for (int t = 0; t < 13; ++t)
                #pragma unroll
                for (int q = 0; q < 4; ++q) acc[s][t][q] = 0.0f;

        for (int c = 0; c < NCHK; ++c) {
            const int g = (l - 1) * NCHK + c;           // global chunk id
            const uint32_t curB = sbase + SM_B + (g & 1) * BUFSZ;
            if (g + 1 < NG) {
                // stage chunk g+1 (possibly next layer's chunk 0) into other buffer
                const char* src = wflat + (size_t)(g + 1) * BUFSZ;
                uint32_t dst = sbase + SM_B + ((g + 1) & 1) * BUFSZ;
                for (int i = tid * 16; i < BUFSZ; i += THREADS * 16)
                    cp16(dst + i, src + i);
                CP_COMMIT();
                CP_WAIT1();       // chunk g fully arrived
            } else {
                CP_WAIT0();
            }
            __syncthreads();      // chunk g visible to all warps

            #pragma unroll
            for (int ks = 0; ks < 2; ++ks) {
                const int kb = c * 32 + ks * 16;
                uint32_t ah[2][4], al[2][4];
                ldsm_x4(ah[0], aHi0 + kb * 2);
                ldsm_x4(ah[1], aHi1 + kb * 2);
                ldsm_x4(al[0], aLo0 + kb * 2);
                ldsm_x4(al[1], aLo1 + kb * 2);
                const uint32_t bk = curB + bOff + ks * 16 * (BNC * 2);
                #pragma unroll
                for (int pr = 0; pr < 6; ++pr) {
                    const int nc = wc * 104 + pr * 16;
                    uint32_t bh[4], bl[4];
                    ldsm_x4t(bh, bk + nc * 2);
                    ldsm_x4t(bl, bk + BPLANE + nc * 2);
                    #pragma unroll
                    for (int s = 0; s < 2; ++s) {
                        mma16816(acc[s][2 * pr],     ah[s], bh[0], bh[1]);
                        mma16816(acc[s][2 * pr],     ah[s], bl[0], bl[1]);
                        mma16816(acc[s][2 * pr],     al[s], bh[0], bh[1]);
                        mma16816(acc[s][2 * pr + 1], ah[s], bh[2], bh[3]);
                        mma16816(acc[s][2 * pr + 1], ah[s], bl[2], bl[3]);
                        mma16816(acc[s][2 * pr + 1], al[s], bh[2], bh[3]);
                    }
                }
                // tile 12 (global cols 96..103): wc0 -> row subtile 0, wc1 -> subtile 1
                {
                    uint32_t bh2[2], bl2[2];
                    ldsm_x2t(bh2, bk + 96 * 2);
                    ldsm_x2t(bl2, bk + BPLANE + 96 * 2);
                    mma16816(acc[wc][12], ah[wc], bh2[0], bh2[1]);
                    mma16816(acc[wc][12], ah[wc], bl2[0], bl2[1]);
                    mma16816(acc[wc][12], al[wc], bh2[0], bh2[1]);
                }
            }
            __syncthreads();   // all reads of curB done before it is restaged
        }

        if (l < 6) {
            // epilogue: bias + relu + hi/lo split back into A
            const float* bias = p.b[l];
            #pragma unroll
            for (int s = 0; s < 2; ++s) {
                const int r0 = wr * 32 + s * 16 + (lane >> 2);
                const int r1 = r0 + 8;
                #pragma unroll
                for (int t = 0; t < 12; ++t) {   // j, j+1 always < 200
                    int j = wc * 104 + t * 8 + 2 * (lane & 3);
                    float bj0 = bias[j], bj1 = bias[j + 1];
                    split_store(sm, r0, j, fmaxf(acc[s][t][0] + bj0, 0.0f),
                                            fmaxf(acc[s][t][1] + bj1, 0.0f));
                    split_store(sm, r1, j, fmaxf(acc[s][t][2] + bj0, 0.0f),
                                            fmaxf(acc[s][t][3] + bj1, 0.0f));
                }
            }
            {   // tile 12: rows of subtile s = wc, global cols 96..103
                const int r0 = wr * 32 + wc * 16 + (lane >> 2);
                const int r1 = r0 + 8;
                int j = 96 + 2 * (lane & 3);
                float bj0 = bias[j], bj1 = bias[j + 1];
                split_store(sm, r0, j, fmaxf(acc[wc][12][0] + bj0, 0.0f),
                                        fmaxf(acc[wc][12][1] + bj1, 0.0f));
                split_store(sm, r1, j, fmaxf(acc[wc][12][2] + bj0, 0.0f),
                                        fmaxf(acc[wc][12][3] + bj1, 0.0f));
            }
            __syncthreads();   // A ready for next layer's ldmatrix
        } else {
            // final: relu(acc + b6) dot W7 -> reduce -> sigmoid
            const float* bias = p.b[6];
            const float* W7   = p.W[7];
            float* red = (float*)(sm + SM_B);
            #pragma unroll
            for (int s = 0; s < 2; ++s) {
                const int r0 = wr * 32 + s * 16 + (lane >> 2);
                const int r1 = r0 + 8;
                float p0 = 0.0f, p1 = 0.0f;
                #pragma unroll
                for (int t = 0; t < 12; ++t) {
                    int j = wc * 104 + t * 8 + 2 * (lane & 3);
                    float bj0 = bias[j], w0 = W7[j];
                    float bj1 = bias[j + 1], w1 = W7[j + 1];
                    p0 = fmaf(fmaxf(acc[s][t][0] + bj0, 0.0f), w0, p0);
                    p0 = fmaf(fmaxf(acc[s][t][1] + bj1, 0.0f), w1, p0);
                    p1 = fmaf(fmaxf(acc[s][t][2] + bj0, 0.0f), w0, p1);
                    p1 = fmaf(fmaxf(acc[s][t][3] + bj1, 0.0f), w1, p1);
                }
                if (s == wc) {   // tile 12 contribution (global cols 96..103)
                    int j = 96 + 2 * (lane & 3);
                    float bj0 = bias[j], w0 = W7[j];
                    float bj1 = bias[j + 1], w1 = W7[j + 1];
                    p0 = fmaf(fmaxf(acc[wc][12][0] + bj0, 0.0f), w0, p0);
                    p0 = fmaf(fmaxf(acc[wc][12][1] + bj1, 0.0f), w1, p0);
                    p1 = fmaf(fmaxf(acc[wc][12][2] + bj0, 0.0f), w0, p1);
                    p1 = fmaf(fmaxf(acc[wc][12][3] + bj1, 0.0f), w1, p1);
                }
                p0 += __shfl_xor_sync(0xffffffff, p0, 1);
                p0 += __shfl_xor_sync(0xffffffff, p0, 2);
                p1 += __shfl_xor_sync(0xffffffff, p1, 1);
                p1 += __shfl_xor_sync(0xffffffff, p1, 2);
                if ((lane & 3) == 0) {
                    red[r0 * 2 + wc] = p0;
                    red[r1 * 2 + wc] = p1;
                }
            }
            __syncthreads();
            if (tid < MT) {
                float s = red[tid * 2] + red[tid * 2 + 1] + p.b[7][0];
                out[row0 + tid] = 1.0f / (1.0f + expf(-s));
            }
        }
    }
}

// ---------------------------------------------------------------------------
extern "C" void kernel_launch(void* const* d_in, const int* in_sizes, int n_in,
                              void* d_out, int out_size) {
    const float* x  = (const float*)d_in[0];
    const void*  ei = d_in[1];
    Params p;
    for (int i = 0; i < 8; ++i) {
        p.W[i] = (const float*)d_in[2 + 2 * i];
        p.b[i] = (const float*)d_in[3 + 2 * i];
    }
    float* out = (float*)d_out;

    cudaFuncSetAttribute(mlp_kernel, cudaFuncAttributeMaxDynamicSharedMemorySize, SMEM_BYTES);

    detect_kernel<<<1, 32>>>((const int*)ei);
    prep_w_kernel<<<(6 * NCHK * 32 * BNC + 255) / 256, 256>>>(p);
    zero_deg_kernel<<<NN / 256, 256>>>();
    deg_kernel<<<2048, 256>>>(ei);
    inv_init_kernel<<<NN / 256, 256>>>(x);
    edge_agg_kernel<<<2048, 256>>>(x, ei);
    mlp_kernel<<<NN / MT, THREADS, SMEM_BYTES>>>(p, out);
}

// round 11
// speedup vs baseline: 3.8307x; 2.4645x over previous
#include <cuda_runtime.h>
#include <cuda_bf16.h>
#include <math.h>
#include <stdint.h>

#define NN   262144
#define EE   2097152
#define HID  200
#define MT   128                 // rows per CTA
#define CAC  232                 // A smem cols (k padded; stride 464B conflict-free)
#define NCHK 7                   // k chunks of 32 (224 >= 200, zero padded)
#define NG   (6 * NCHK)          // 42 global chunks across layers 1..6
#define BNC  216                 // B smem cols (n padded; stride 432B conflict-free)
#define SA_PLANE (MT * CAC * 2)          // 59392 B per A plane
#define SM_A_HI  0
#define SM_A_LO  SA_PLANE
#define SM_B     (2 * SA_PLANE)          // 118784
#define BPLANE   (32 * BNC * 2)          // 13824 B
#define BUFSZ    (2 * BPLANE)            // 27648 B (hi+lo)
#define SMEM_BYTES (SM_B + 2 * BUFSZ)    // 174080
#define THREADS  256

// ------------------------- device globals (scratch) -------------------------
__device__ float g_deg[NN];
__device__ float g_inv[NN];
__device__ float g_agg[NN];
__device__ int   g_is64;
// weights pre-split bf16 hi/lo: [layer 1..6][chunk][plane][k32][BNC]
__device__ __align__(16) __nv_bfloat16 g_wtB[6][NCHK][2][32][BNC];

struct Params {
    const float* W[8];
    const float* b[8];
};

// ------------------------------- PTX helpers --------------------------------
__device__ __forceinline__ uint32_t smem_u32(const void* p) {
    uint32_t a;
    asm("{ .reg .u64 t; cvta.to.shared.u64 t, %1; cvt.u32.u64 %0, t; }" : "=r"(a) : "l"(p));
    return a;
}
__device__ __forceinline__ void cp16(uint32_t sdst, const void* gsrc) {
    asm volatile("cp.async.cg.shared.global [%0], [%1], 16;" :: "r"(sdst), "l"(gsrc));
}
#define CP_COMMIT() asm volatile("cp.async.commit_group;")
#define CP_WAIT1()  asm volatile("cp.async.wait_group 1;")
#define CP_WAIT0()  asm volatile("cp.async.wait_group 0;")

__device__ __forceinline__ void ldsm_x4(uint32_t* r, uint32_t addr) {
    asm volatile("ldmatrix.sync.aligned.m8n8.x4.shared.b16 {%0,%1,%2,%3}, [%4];"
                 : "=r"(r[0]), "=r"(r[1]), "=r"(r[2]), "=r"(r[3]) : "r"(addr));
}
__device__ __forceinline__ void ldsm_x4t(uint32_t* r, uint32_t addr) {
    asm volatile("ldmatrix.sync.aligned.m8n8.x4.trans.shared.b16 {%0,%1,%2,%3}, [%4];"
                 : "=r"(r[0]), "=r"(r[1]), "=r"(r[2]), "=r"(r[3]) : "r"(addr));
}
__device__ __forceinline__ void ldsm_x2t(uint32_t* r, uint32_t addr) {
    asm volatile("ldmatrix.sync.aligned.m8n8.x2.trans.shared.b16 {%0,%1}, [%2];"
                 : "=r"(r[0]), "=r"(r[1]) : "r"(addr));
}
__device__ __forceinline__ void mma16816(float* d, const uint32_t* a, uint32_t b0, uint32_t b1) {
    asm volatile(
        "mma.sync.aligned.m16n8k16.row.col.f32.bf16.bf16.f32 "
        "{%0,%1,%2,%3}, {%4,%5,%6,%7}, {%8,%9}, {%0,%1,%2,%3};"
        : "+f"(d[0]), "+f"(d[1]), "+f"(d[2]), "+f"(d[3])
        : "r"(a[0]), "r"(a[1]), "r"(a[2]), "r"(a[3]), "r"(b0), "r"(b1));
}

// ------------------------- edge aggregation kernels -------------------------
__global__ void detect_kernel(const int* __restrict__ ei32) {
    if (blockIdx.x == 0 && threadIdx.x == 0) {
        int orv = 0;
        for (int i = 1; i < 128; i += 2) orv |= ei32[i];
        g_is64 = (orv == 0) ? 1 : 0;
    }
}
__device__ __forceinline__ int load_idx(const void* ei, long long pos, int is64) {
    if (is64) return (int)((const long long*)ei)[pos];
    return ((const int*)ei)[pos];
}
__global__ void zero_deg_kernel() {
    int i = blockIdx.x * blockDim.x + threadIdx.x;
    if (i < NN) g_deg[i] = 0.0f;
}
__global__ void deg_kernel(const void* __restrict__ ei) {
    const int is64 = g_is64;
    long long stride = (long long)gridDim.x * blockDim.x;
    for (long long e = (long long)blockIdx.x * blockDim.x + threadIdx.x; e < EE; e += stride) {
        int d = load_idx(ei, (long long)EE + e, is64);
        atomicAdd(&g_deg[d], 1.0f);
    }
}
__global__ void inv_init_kernel(const float* __restrict__ x) {
    int i = blockIdx.x * blockDim.x + threadIdx.x;
    if (i < NN) {
        float inv = rsqrtf(g_deg[i] + 1.0f);
        g_inv[i] = inv;
        g_agg[i] = x[i] * inv * inv;
    }
}
__global__ void edge_agg_kernel(const float* __restrict__ x, const void* __restrict__ ei) {
    const int is64 = g_is64;
    long long stride = (long long)gridDim.x * blockDim.x;
    for (long long e = (long long)blockIdx.x * blockDim.x + threadIdx.x; e < EE; e += stride) {
        int s = load_idx(ei, e, is64);
        int d = load_idx(ei, (long long)EE + e, is64);
        atomicAdd(&g_agg[d], x[s] * g_inv[s] * g_inv[d]);
    }
}

// ------------------- weight prep: fp32 -> bf16 hi/lo planes -----------------
__global__ void prep_w_kernel(Params p) {
    int idx = blockIdx.x * blockDim.x + threadIdx.x;
    const int total = 6 * NCHK * 32 * BNC;
    if (idx >= total) return;
    int n = idx % BNC;
    int k = (idx / BNC) % 32;
    int c = (idx / (BNC * 32)) % NCHK;
    int l = idx / (BNC * 32 * NCHK);
    int kg = c * 32 + k;
    float v = 0.0f;
    if (kg < HID && n < HID) v = p.W[l + 1][kg * HID + n];
    __nv_bfloat16 hi = __float2bfloat16(v);
    __nv_bfloat16 lo = __float2bfloat16(v - __bfloat162float(hi));
    g_wtB[l][c][0][k][n] = hi;
    g_wtB[l][c][1][k][n] = lo;
}

// ------------------------------ fused MLP kernel ----------------------------
__device__ __forceinline__ void split_store(char* sm, int r, int j, float v0, float v1) {
    __nv_bfloat16 h0 = __float2bfloat16(v0), h1 = __float2bfloat16(v1);
    __nv_bfloat16 l0 = __float2bfloat16(v0 - __bfloat162float(h0));
    __nv_bfloat16 l1 = __float2bfloat16(v1 - __bfloat162float(h1));
    uint32_t hp = (uint32_t)__bfloat16_as_ushort(h0) | ((uint32_t)__bfloat16_as_ushort(h1) << 16);
    uint32_t lp = (uint32_t)__bfloat16_as_ushort(l0) | ((uint32_t)__bfloat16_as_ushort(l1) << 16);
    *(uint32_t*)(sm + SM_A_HI + r * (CAC * 2) + j * 2) = hp;
    *(uint32_t*)(sm + SM_A_LO + r * (CAC * 2) + j * 2) = lp;
}

__global__ void __launch_bounds__(THREADS, 1) mlp_kernel(Params p, float* __restrict__ out) {
    extern __shared__ char sm[];
    const uint32_t sbase = smem_u32(sm);
    const int tid  = threadIdx.x;
    const int wid  = tid >> 5;
    const int lane = tid & 31;
    const int wr   = wid & 3;       // row group: rows 32*wr..+31 (two m16 subtiles)
    const int wc   = wid >> 2;      // col half: cols 104*wc..+103
    const int row0 = blockIdx.x * MT;

    // ldmatrix lane address components
    const int mrow  = (lane & 7) + 8 * ((lane >> 3) & 1);
    const int koff8 = 8 * (lane >> 4);
    const uint32_t aHi0 = sbase + SM_A_HI + (wr * 32 + mrow) * (CAC * 2) + koff8 * 2;
    const uint32_t aLo0 = sbase + SM_A_LO + (wr * 32 + mrow) * (CAC * 2) + koff8 * 2;
    const uint32_t aHi1 = aHi0 + 16 * (CAC * 2);
    const uint32_t aLo1 = aLo0 + 16 * (CAC * 2);
    const uint32_t bOff = (uint32_t)(mrow * (BNC * 2) + koff8 * 2);

    const char* wflat = (const char*)&g_wtB[0][0][0][0][0];

    // stage global chunk 0 into buffer 0 (overlaps with layer-0 gather below)
    for (int i = tid * 16; i < BUFSZ; i += THREADS * 16)
        cp16(sbase + SM_B + i, wflat + i);
    CP_COMMIT();

    // ---- layer 0: A = relu(agg * W0 + b0) -> bf16 hi/lo, zero padding ----
    {
        const float* W0 = p.W[0];
        const float* b0 = p.b[0];
        for (int idx = tid; idx < MT * (CAC / 2); idx += THREADS) {
            int r = idx / (CAC / 2);
            int j = (idx - r * (CAC / 2)) * 2;
            float agg = g_agg[row0 + r];
            float v0 = (j < HID)     ? fmaxf(fmaf(agg, W0[j],     b0[j]),     0.0f) : 0.0f;
            float v1 = (j + 1 < HID) ? fmaxf(fmaf(agg, W0[j + 1], b0[j + 1]), 0.0f) : 0.0f;
            split_store(sm, r, j, v0, v1);
        }
    }
    __syncthreads();

    for (int l = 1; l <= 6; ++l) {
        float acc[2][13][4];
        #pragma unroll
        for (int s = 0; s < 2; ++s)
            #pragma unroll
            for (int t = 0; t < 13; ++t)
                #pragma unroll
                for (int q = 0; q < 4; ++q) acc[s][t][q] = 0.0f;
        float acc12[4] = {0.0f, 0.0f, 0.0f, 0.0f};   // tile 12 (rows subtile = wc)

        for (int c = 0; c < NCHK; ++c) {
            const int g = (l - 1) * NCHK + c;           // global chunk id
            const uint32_t curB = sbase + SM_B + (g & 1) * BUFSZ;
            if (g + 1 < NG) {
                // stage chunk g+1 (possibly next layer's chunk 0) into other buffer
                const char* src = wflat + (size_t)(g + 1) * BUFSZ;
                uint32_t dst = sbase + SM_B + ((g + 1) & 1) * BUFSZ;
                for (int i = tid * 16; i < BUFSZ; i += THREADS * 16)
                    cp16(dst + i, src + i);
                CP_COMMIT();
                CP_WAIT1();       // chunk g fully arrived
            } else {
                CP_WAIT0();
            }
            __syncthreads();      // chunk g visible to all warps

            #pragma unroll
            for (int ks = 0; ks < 2; ++ks) {
                const int kb = c * 32 + ks * 16;
                uint32_t ah[2][4], al[2][4];
                ldsm_x4(ah[0], aHi0 + kb * 2);
                ldsm_x4(ah[1], aHi1 + kb * 2);
                ldsm_x4(al[0], aLo0 + kb * 2);
                ldsm_x4(al[1], aLo1 + kb * 2);
                const uint32_t bk = curB + bOff + ks * 16 * (BNC * 2);
                #pragma unroll
                for (int pr = 0; pr < 6; ++pr) {
                    const int nc = wc * 104 + pr * 16;
                    uint32_t bh[4], bl[4];
                    ldsm_x4t(bh, bk + nc * 2);
                    ldsm_x4t(bl, bk + BPLANE + nc * 2);
                    #pragma unroll
                    for (int s = 0; s < 2; ++s) {
                        mma16816(acc[s][2 * pr],     ah[s], bh[0], bh[1]);
                        mma16816(acc[s][2 * pr],     ah[s], bl[0], bl[1]);
                        mma16816(acc[s][2 * pr],     al[s], bh[0], bh[1]);
                        mma16816(acc[s][2 * pr + 1], ah[s], bh[2], bh[3]);
                        mma16816(acc[s][2 * pr + 1], ah[s], bl[2], bl[3]);
                        mma16816(acc[s][2 * pr + 1], al[s], bh[2], bh[3]);
                    }
                }
                // tile 12 (global cols 96..103): wc0 -> row subtile 0, wc1 -> subtile 1.
                // Uniform branch, all register names static (no dynamic indexing!).
                {
                    uint32_t bh2[2], bl2[2];
                    ldsm_x2t(bh2, bk + 96 * 2);
                    ldsm_x2t(bl2, bk + BPLANE + 96 * 2);
                    if (wc == 0) {
                        mma16816(acc12, ah[0], bh2[0], bh2[1]);
                        mma16816(acc12, ah[0], bl2[0], bl2[1]);
                        mma16816(acc12, al[0], bh2[0], bh2[1]);
                    } else {
                        mma16816(acc12, ah[1], bh2[0], bh2[1]);
                        mma16816(acc12, ah[1], bl2[0], bl2[1]);
                        mma16816(acc12, al[1], bh2[0], bh2[1]);
                    }
                }
            }
            __syncthreads();   // all reads of curB done before it is restaged
        }

        if (l < 6) {
            // epilogue: bias + relu + hi/lo split back into A
            const float* bias = p.b[l];
            #pragma unroll
            for (int s = 0; s < 2; ++s) {
                const int r0 = wr * 32 + s * 16 + (lane >> 2);
                const int r1 = r0 + 8;
                #pragma unroll
                for (int t = 0; t < 12; ++t) {   // j, j+1 always < 200
                    int j = wc * 104 + t * 8 + 2 * (lane & 3);
                    float bj0 = bias[j], bj1 = bias[j + 1];
                    split_store(sm, r0, j, fmaxf(acc[s][t][0] + bj0, 0.0f),
                                            fmaxf(acc[s][t][1] + bj1, 0.0f));
                    split_store(sm, r1, j, fmaxf(acc[s][t][2] + bj0, 0.0f),
                                            fmaxf(acc[s][t][3] + bj1, 0.0f));
                }
            }
            {   // tile 12: rows of subtile s = wc, global cols 96..103
                const int r0 = wr * 32 + wc * 16 + (lane >> 2);
                const int r1 = r0 + 8;
                int j = 96 + 2 * (lane & 3);
                float bj0 = bias[j], bj1 = bias[j + 1];
                split_store(sm, r0, j, fmaxf(acc12[0] + bj0, 0.0f),
                                        fmaxf(acc12[1] + bj1, 0.0f));
                split_store(sm, r1, j, fmaxf(acc12[2] + bj0, 0.0f),
                                        fmaxf(acc12[3] + bj1, 0.0f));
            }
            __syncthreads();   // A ready for next layer's ldmatrix
        } else {
            // final: relu(acc + b6) dot W7 -> reduce -> sigmoid
            const float* bias = p.b[6];
            const float* W7   = p.W[7];
            float* red = (float*)(sm + SM_B);
            #pragma unroll
            for (int s = 0; s < 2; ++s) {
                const int r0 = wr * 32 + s * 16 + (lane >> 2);
                const int r1 = r0 + 8;
                float p0 = 0.0f, p1 = 0.0f;
                #pragma unroll
                for (int t = 0; t < 12; ++t) {
                    int j = wc * 104 + t * 8 + 2 * (lane & 3);
                    float bj0 = bias[j], w0 = W7[j];
                    float bj1 = bias[j + 1], w1 = W7[j + 1];
                    p0 = fmaf(fmaxf(acc[s][t][0] + bj0, 0.0f), w0, p0);
                    p0 = fmaf(fmaxf(acc[s][t][1] + bj1, 0.0f), w1, p0);
                    p1 = fmaf(fmaxf(acc[s][t][2] + bj0, 0.0f), w0, p1);
                    p1 = fmaf(fmaxf(acc[s][t][3] + bj1, 0.0f), w1, p1);
                }
                if (s == wc) {   // tile 12 contribution (static acc12)
                    int j = 96 + 2 * (lane & 3);
                    float bj0 = bias[j], w0 = W7[j];
                    float bj1 = bias[j + 1], w1 = W7[j + 1];
                    p0 = fmaf(fmaxf(acc12[0] + bj0, 0.0f), w0, p0);
                    p0 = fmaf(fmaxf(acc12[1] + bj1, 0.0f), w1, p0);
                    p1 = fmaf(fmaxf(acc12[2] + bj0, 0.0f), w0, p1);
                    p1 = fmaf(fmaxf(acc12[3] + bj1, 0.0f), w1, p1);
                }
                p0 += __shfl_xor_sync(0xffffffff, p0, 1);
                p0 += __shfl_xor_sync(0xffffffff, p0, 2);
                p1 += __shfl_xor_sync(0xffffffff, p1, 1);
                p1 += __shfl_xor_sync(0xffffffff, p1, 2);
                if ((lane & 3) == 0) {
                    red[r0 * 2 + wc] = p0;
                    red[r1 * 2 + wc] = p1;
                }
            }
            __syncthreads();
            if (tid < MT) {
                float s = red[tid * 2] + red[tid * 2 + 1] + p.b[7][0];
                out[row0 + tid] = 1.0f / (1.0f + expf(-s));
            }
        }
    }
}

// ---------------------------------------------------------------------------
extern "C" void kernel_launch(void* const* d_in, const int* in_sizes, int n_in,
                              void* d_out, int out_size) {
    const float* x  = (const float*)d_in[0];
    const void*  ei = d_in[1];
    Params p;
    for (int i = 0; i < 8; ++i) {
        p.W[i] = (const float*)d_in[2 + 2 * i];
        p.b[i] = (const float*)d_in[3 + 2 * i];
    }
    float* out = (float*)d_out;

    cudaFuncSetAttribute(mlp_kernel, cudaFuncAttributeMaxDynamicSharedMemorySize, SMEM_BYTES);

    detect_kernel<<<1, 32>>>((const int*)ei);
    prep_w_kernel<<<(6 * NCHK * 32 * BNC + 255) / 256, 256>>>(p);
    zero_deg_kernel<<<NN / 256, 256>>>();
    deg_kernel<<<2048, 256>>>(ei);
    inv_init_kernel<<<NN / 256, 256>>>(x);
    edge_agg_kernel<<<2048, 256>>>(x, ei);
    mlp_kernel<<<NN / MT, THREADS, SMEM_BYTES>>>(p, out);
}

// round 12
// speedup vs baseline: 4.8232x; 1.2591x over previous
#include <cuda_runtime.h>
#include <cuda_fp16.h>
#include <math.h>
#include <stdint.h>

#define NN   262144
#define EE   2097152
#define HID  200
#define MT   128                 // rows per CTA
#define CAC  232                 // A smem cols (k padded; stride 464B conflict-free)
#define NCHK 7                   // k chunks of 32 (224 >= 200, zero padded)
#define NG   (6 * NCHK)          // 42 global chunks across layers 1..6
#define BNC  216                 // B smem cols (n padded; stride 432B conflict-free)
#define SA_PLANE (MT * CAC * 2)          // 59392 B per A plane
#define SM_A_HI  0
#define SM_A_LO  SA_PLANE
#define SM_B     (2 * SA_PLANE)          // 118784
#define BUFSZ    (32 * BNC * 2)          // 13824 B (single fp16 plane)
#define SMEM_BYTES (SM_B + 2 * BUFSZ)    // 146432
#define THREADS  256

// ------------------------- device globals (scratch) -------------------------
__device__ float g_deg[NN];
__device__ float g_inv[NN];
__device__ float g_agg[NN];
__device__ int   g_is64;
// weights as single fp16 plane: [layer 1..6][chunk][k32][BNC]
__device__ __align__(16) __half g_wtH[6][NCHK][32][BNC];

struct Params {
    const float* W[8];
    const float* b[8];
};

// ------------------------------- PTX helpers --------------------------------
__device__ __forceinline__ uint32_t smem_u32(const void* p) {
    uint32_t a;
    asm("{ .reg .u64 t; cvta.to.shared.u64 t, %1; cvt.u32.u64 %0, t; }" : "=r"(a) : "l"(p));
    return a;
}
__device__ __forceinline__ void cp16(uint32_t sdst, const void* gsrc) {
    asm volatile("cp.async.cg.shared.global [%0], [%1], 16;" :: "r"(sdst), "l"(gsrc));
}
#define CP_COMMIT() asm volatile("cp.async.commit_group;")
#define CP_WAIT1()  asm volatile("cp.async.wait_group 1;")
#define CP_WAIT0()  asm volatile("cp.async.wait_group 0;")

__device__ __forceinline__ void ldsm_x4(uint32_t* r, uint32_t addr) {
    asm volatile("ldmatrix.sync.aligned.m8n8.x4.shared.b16 {%0,%1,%2,%3}, [%4];"
                 : "=r"(r[0]), "=r"(r[1]), "=r"(r[2]), "=r"(r[3]) : "r"(addr));
}
__device__ __forceinline__ void ldsm_x4t(uint32_t* r, uint32_t addr) {
    asm volatile("ldmatrix.sync.aligned.m8n8.x4.trans.shared.b16 {%0,%1,%2,%3}, [%4];"
                 : "=r"(r[0]), "=r"(r[1]), "=r"(r[2]), "=r"(r[3]) : "r"(addr));
}
__device__ __forceinline__ void ldsm_x2t(uint32_t* r, uint32_t addr) {
    asm volatile("ldmatrix.sync.aligned.m8n8.x2.trans.shared.b16 {%0,%1}, [%2];"
                 : "=r"(r[0]), "=r"(r[1]) : "r"(addr));
}
__device__ __forceinline__ void mma16816(float* d, const uint32_t* a, uint32_t b0, uint32_t b1) {
    asm volatile(
        "mma.sync.aligned.m16n8k16.row.col.f32.f16.f16.f32 "
        "{%0,%1,%2,%3}, {%4,%5,%6,%7}, {%8,%9}, {%0,%1,%2,%3};"
        : "+f"(d[0]), "+f"(d[1]), "+f"(d[2]), "+f"(d[3])
        : "r"(a[0]), "r"(a[1]), "r"(a[2]), "r"(a[3]), "r"(b0), "r"(b1));
}

// ------------------------- edge aggregation kernels -------------------------
__global__ void detect_kernel(const int* __restrict__ ei32) {
    if (blockIdx.x == 0 && threadIdx.x == 0) {
        int orv = 0;
        for (int i = 1; i < 128; i += 2) orv |= ei32[i];
        g_is64 = (orv == 0) ? 1 : 0;
    }
}
__device__ __forceinline__ int load_idx(const void* ei, long long pos, int is64) {
    if (is64) return (int)((const long long*)ei)[pos];
    return ((const int*)ei)[pos];
}
__global__ void zero_deg_kernel() {
    int i = blockIdx.x * blockDim.x + threadIdx.x;
    if (i < NN) g_deg[i] = 0.0f;
}
__global__ void deg_kernel(const void* __restrict__ ei) {
    const int is64 = g_is64;
    long long stride = (long long)gridDim.x * blockDim.x;
    for (long long e = (long long)blockIdx.x * blockDim.x + threadIdx.x; e < EE; e += stride) {
        int d = load_idx(ei, (long long)EE + e, is64);
        atomicAdd(&g_deg[d], 1.0f);
    }
}
__global__ void inv_init_kernel(const float* __restrict__ x) {
    int i = blockIdx.x * blockDim.x + threadIdx.x;
    if (i < NN) {
        float inv = rsqrtf(g_deg[i] + 1.0f);
        g_inv[i] = inv;
        g_agg[i] = x[i] * inv * inv;
    }
}
__global__ void edge_agg_kernel(const float* __restrict__ x, const void* __restrict__ ei) {
    const int is64 = g_is64;
    long long stride = (long long)gridDim.x * blockDim.x;
    for (long long e = (long long)blockIdx.x * blockDim.x + threadIdx.x; e < EE; e += stride) {
        int s = load_idx(ei, e, is64);
        int d = load_idx(ei, (long long)EE + e, is64);
        atomicAdd(&g_agg[d], x[s] * g_inv[s] * g_inv[d]);
    }
}

// ------------------- weight prep: fp32 -> single fp16 plane -----------------
__global__ void prep_w_kernel(Params p) {
    int idx = blockIdx.x * blockDim.x + threadIdx.x;
    const int total = 6 * NCHK * 32 * BNC;
    if (idx >= total) return;
    int n = idx % BNC;
    int k = (idx / BNC) % 32;
    int c = (idx / (BNC * 32)) % NCHK;
    int l = idx / (BNC * 32 * NCHK);
    int kg = c * 32 + k;
    float v = 0.0f;
    if (kg < HID && n < HID) v = p.W[l + 1][kg * HID + n];
    g_wtH[l][c][k][n] = __float2half_rn(v);
}

// ------------------------------ fused MLP kernel ----------------------------
// A stored as fp16 hi/lo pair: a = ah + al exact to ~2^-22.
__device__ __forceinline__ void split_store(char* sm, int r, int j, float v0, float v1) {
    __half h0 = __float2half_rn(v0), h1 = __float2half_rn(v1);
    __half l0 = __float2half_rn(v0 - __half2float(h0));
    __half l1 = __float2half_rn(v1 - __half2float(h1));
    uint32_t hp = (uint32_t)__half_as_ushort(h0) | ((uint32_t)__half_as_ushort(h1) << 16);
    uint32_t lp = (uint32_t)__half_as_ushort(l0) | ((uint32_t)__half_as_ushort(l1) << 16);
    *(uint32_t*)(sm + SM_A_HI + r * (CAC * 2) + j * 2) = hp;
    *(uint32_t*)(sm + SM_A_LO + r * (CAC * 2) + j * 2) = lp;
}

__global__ void __launch_bounds__(THREADS, 1) mlp_kernel(Params p, float* __restrict__ out) {
    extern __shared__ char sm[];
    const uint32_t sbase = smem_u32(sm);
    const int tid  = threadIdx.x;
    const int wid  = tid >> 5;
    const int lane = tid & 31;
    const int wr   = wid & 3;       // row group: rows 32*wr..+31 (two m16 subtiles)
    const int wc   = wid >> 2;      // col half: cols 104*wc..+103
    const int row0 = blockIdx.x * MT;

    // ldmatrix lane address components
    const int mrow  = (lane & 7) + 8 * ((lane >> 3) & 1);
    const int koff8 = 8 * (lane >> 4);
    const uint32_t aHi0 = sbase + SM_A_HI + (wr * 32 + mrow) * (CAC * 2) + koff8 * 2;
    const uint32_t aLo0 = sbase + SM_A_LO + (wr * 32 + mrow) * (CAC * 2) + koff8 * 2;
    const uint32_t aHi1 = aHi0 + 16 * (CAC * 2);
    const uint32_t aLo1 = aLo0 + 16 * (CAC * 2);
    const uint32_t bOff = (uint32_t)(mrow * (BNC * 2) + koff8 * 2);

    const char* wflat = (const char*)&g_wtH[0][0][0][0];

    // stage global chunk 0 into buffer 0 (overlaps with layer-0 gather below)
    for (int i = tid * 16; i < BUFSZ; i += THREADS * 16)
        cp16(sbase + SM_B + i, wflat + i);
    CP_COMMIT();

    // ---- layer 0: A = relu(agg * W0 + b0) -> fp16 hi/lo, zero padding ----
    {
        const float* W0 = p.W[0];
        const float* b0 = p.b[0];
        for (int idx = tid; idx < MT * (CAC / 2); idx += THREADS) {
            int r = idx / (CAC / 2);
            int j = (idx - r * (CAC / 2)) * 2;
            float agg = g_agg[row0 + r];
            float v0 = (j < HID)     ? fmaxf(fmaf(agg, W0[j],     b0[j]),     0.0f) : 0.0f;
            float v1 = (j + 1 < HID) ? fmaxf(fmaf(agg, W0[j + 1], b0[j + 1]), 0.0f) : 0.0f;
            split_store(sm, r, j, v0, v1);
        }
    }
    __syncthreads();

    for (int l = 1; l <= 6; ++l) {
        float acc[2][13][4];
        #pragma unroll
        for (int s = 0; s < 2; ++s)
            #pragma unroll
            for (int t = 0; t < 13; ++t)
                #pragma unroll
                for (int q = 0; q < 4; ++q) acc[s][t][q] = 0.0f;
        float acc12[4] = {0.0f, 0.0f, 0.0f, 0.0f};   // tile 12 (rows subtile = wc)

        for (int c = 0; c < NCHK; ++c) {
            const int g = (l - 1) * NCHK + c;           // global chunk id
            const uint32_t curB = sbase + SM_B + (g & 1) * BUFSZ;
            if (g + 1 < NG) {
                // stage chunk g+1 (possibly next layer's chunk 0) into other buffer
                const char* src = wflat + (size_t)(g + 1) * BUFSZ;
                uint32_t dst = sbase + SM_B + ((g + 1) & 1) * BUFSZ;
                for (int i = tid * 16; i < BUFSZ; i += THREADS * 16)
                    cp16(dst + i, src + i);
                CP_COMMIT();
                CP_WAIT1();       // chunk g fully arrived
            } else {
                CP_WAIT0();
            }
            __syncthreads();      // chunk g visible to all warps

            #pragma unroll
            for (int ks = 0; ks < 2; ++ks) {
                const int kb = c * 32 + ks * 16;
                uint32_t ah[2][4], al[2][4];
                ldsm_x4(ah[0], aHi0 + kb * 2);
                ldsm_x4(ah[1], aHi1 + kb * 2);
                ldsm_x4(al[0], aLo0 + kb * 2);
                ldsm_x4(al[1], aLo1 + kb * 2);
                const uint32_t bk = curB + bOff + ks * 16 * (BNC * 2);
                #pragma unroll
                for (int pr = 0; pr < 6; ++pr) {
                    const int nc = wc * 104 + pr * 16;
                    uint32_t bh[4];
                    ldsm_x4t(bh, bk + nc * 2);
                    #pragma unroll
                    for (int s = 0; s < 2; ++s) {
                        mma16816(acc[s][2 * pr],     ah[s], bh[0], bh[1]);
                        mma16816(acc[s][2 * pr],     al[s], bh[0], bh[1]);
                        mma16816(acc[s][2 * pr + 1], ah[s], bh[2], bh[3]);
                        mma16816(acc[s][2 * pr + 1], al[s], bh[2], bh[3]);
                    }
                }
                // tile 12 (global cols 96..103): wc0 -> row subtile 0, wc1 -> subtile 1.
                // Uniform branch, all register names static (no dynamic indexing!).
                {
                    uint32_t bh2[2];
                    ldsm_x2t(bh2, bk + 96 * 2);
                    if (wc == 0) {
                        mma16816(acc12, ah[0], bh2[0], bh2[1]);
                        mma16816(acc12, al[0], bh2[0], bh2[1]);
                    } else {
                        mma16816(acc12, ah[1], bh2[0], bh2[1]);
                        mma16816(acc12, al[1], bh2[0], bh2[1]);
                    }
                }
            }
            __syncthreads();   // all reads of curB done before it is restaged
        }

        if (l < 6) {
            // epilogue: bias + relu + fp16 hi/lo split back into A
            const float* bias = p.b[l];
            #pragma unroll
            for (int s = 0; s < 2; ++s) {
                const int r0 = wr * 32 + s * 16 + (lane >> 2);
                const int r1 = r0 + 8;
                #pragma unroll
                for (int t = 0; t < 12; ++t) {   // j, j+1 always < 200
                    int j = wc * 104 + t * 8 + 2 * (lane & 3);
                    float bj0 = bias[j], bj1 = bias[j + 1];
                    split_store(sm, r0, j, fmaxf(acc[s][t][0] + bj0, 0.0f),
                                            fmaxf(acc[s][t][1] + bj1, 0.0f));
                    split_store(sm, r1, j, fmaxf(acc[s][t][2] + bj0, 0.0f),
                                            fmaxf(acc[s][t][3] + bj1, 0.0f));
                }
            }
            {   // tile 12: rows of subtile s = wc, global cols 96..103
                const int r0 = wr * 32 + wc * 16 + (lane >> 2);
                const int r1 = r0 + 8;
                int j = 96 + 2 * (lane & 3);
                float bj0 = bias[j], bj1 = bias[j + 1];
                split_store(sm, r0, j, fmaxf(acc12[0] + bj0, 0.0f),
                                        fmaxf(acc12[1] + bj1, 0.0f));
                split_store(sm, r1, j, fmaxf(acc12[2] + bj0, 0.0f),
                                        fmaxf(acc12[3] + bj1, 0.0f));
            }
            __syncthreads();   // A ready for next layer's ldmatrix
        } else {
            // final: relu(acc + b6) dot W7 -> reduce -> sigmoid
            const float* bias = p.b[6];
            const float* W7   = p.W[7];
            float* red = (float*)(sm + SM_B);
            #pragma unroll
            for (int s = 0; s < 2; ++s) {
                const int r0 = wr * 32 + s * 16 + (lane >> 2);
                const int r1 = r0 + 8;
                float p0 = 0.0f, p1 = 0.0f;
                #pragma unroll
                for (int t = 0; t < 12; ++t) {
                    int j = wc * 104 + t * 8 + 2 * (lane & 3);
                    float bj0 = bias[j], w0 = W7[j];
                    float bj1 = bias[j + 1], w1 = W7[j + 1];
                    p0 = fmaf(fmaxf(acc[s][t][0] + bj0, 0.0f), w0, p0);
                    p0 = fmaf(fmaxf(acc[s][t][1] + bj1, 0.0f), w1, p0);
                    p1 = fmaf(fmaxf(acc[s][t][2] + bj0, 0.0f), w0, p1);
                    p1 = fmaf(fmaxf(acc[s][t][3] + bj1, 0.0f), w1, p1);
                }
                if (s == wc) {   // tile 12 contribution (static acc12)
                    int j = 96 + 2 * (lane & 3);
                    float bj0 = bias[j], w0 = W7[j];
                    float bj1 = bias[j + 1], w1 = W7[j + 1];
                    p0 = fmaf(fmaxf(acc12[0] + bj0, 0.0f), w0, p0);
                    p0 = fmaf(fmaxf(acc12[1] + bj1, 0.0f), w1, p0);
                    p1 = fmaf(fmaxf(acc12[2] + bj0, 0.0f), w0, p1);
                    p1 = fmaf(fmaxf(acc12[3] + bj1, 0.0f), w1, p1);
                }
                p0 += __shfl_xor_sync(0xffffffff, p0, 1);
                p0 += __shfl_xor_sync(0xffffffff, p0, 2);
                p1 += __shfl_xor_sync(0xffffffff, p1, 1);
                p1 += __shfl_xor_sync(0xffffffff, p1, 2);
                if ((lane & 3) == 0) {
                    red[r0 * 2 + wc] = p0;
                    red[r1 * 2 + wc] = p1;
                }
            }
            __syncthreads();
            if (tid < MT) {
                float s = red[tid * 2] + red[tid * 2 + 1] + p.b[7][0];
                out[row0 + tid] = 1.0f / (1.0f + expf(-s));
            }
        }
    }
}

// ---------------------------------------------------------------------------
extern "C" void kernel_launch(void* const* d_in, const int* in_sizes, int n_in,
                              void* d_out, int out_size) {
    const float* x  = (const float*)d_in[0];
    const void*  ei = d_in[1];
    Params p;
    for (int i = 0; i < 8; ++i) {
        p.W[i] = (const float*)d_in[2 + 2 * i];
        p.b[i] = (const float*)d_in[3 + 2 * i];
    }
    float* out = (float*)d_out;

    cudaFuncSetAttribute(mlp_kernel, cudaFuncAttributeMaxDynamicSharedMemorySize, SMEM_BYTES);

    detect_kernel<<<1, 32>>>((const int*)ei);
    prep_w_kernel<<<(6 * NCHK * 32 * BNC + 255) / 256, 256>>>(p);
    zero_deg_kernel<<<NN / 256, 256>>>();
    deg_kernel<<<2048, 256>>>(ei);
    inv_init_kernel<<<NN / 256, 256>>>(x);
    edge_agg_kernel<<<2048, 256>>>(x, ei);
    mlp_kernel<<<NN / MT, THREADS, SMEM_BYTES>>>(p, out);
}

// round 13
// speedup vs baseline: 7.6602x; 1.5882x over previous
#include <cuda_runtime.h>
#include <cuda_fp16.h>
#include <math.h>
#include <stdint.h>

#define NN   262144
#define EE   2097152
#define HID  200
#define MT   128                 // rows per CTA
#define CAC  232                 // A smem cols (k padded; stride 464B conflict-free)
#define NCHK 7                   // k chunks of 32 (224 >= 200, zero padded)
#define NG   (6 * NCHK)          // 42 global chunks across layers 1..6
#define BNC  216                 // B smem cols (n padded; stride 432B conflict-free)
#define SA_PLANE (MT * CAC * 2)          // 59392 B (single fp16 A plane)
#define SM_A     0
#define SM_B     SA_PLANE
#define BUFSZ    (32 * BNC * 2)          // 13824 B (single fp16 B plane)
#define SMEM_BYTES (SM_B + 2 * BUFSZ)    // 87040
#define THREADS  256

// ------------------------- device globals (scratch) -------------------------
__device__ float g_deg[NN];
__device__ float g_inv[NN];
__device__ float g_agg[NN];
__device__ int   g_is64;
// weights as single fp16 plane: [layer 1..6][chunk][k32][BNC]
__device__ __align__(16) __half g_wtH[6][NCHK][32][BNC];

struct Params {
    const float* W[8];
    const float* b[8];
};

// ------------------------------- PTX helpers --------------------------------
__device__ __forceinline__ uint32_t smem_u32(const void* p) {
    uint32_t a;
    asm("{ .reg .u64 t; cvta.to.shared.u64 t, %1; cvt.u32.u64 %0, t; }" : "=r"(a) : "l"(p));
    return a;
}
__device__ __forceinline__ void cp16(uint32_t sdst, const void* gsrc) {
    asm volatile("cp.async.cg.shared.global [%0], [%1], 16;" :: "r"(sdst), "l"(gsrc));
}
#define CP_COMMIT() asm volatile("cp.async.commit_group;")
#define CP_WAIT1()  asm volatile("cp.async.wait_group 1;")
#define CP_WAIT0()  asm volatile("cp.async.wait_group 0;")

__device__ __forceinline__ void ldsm_x4(uint32_t* r, uint32_t addr) {
    asm volatile("ldmatrix.sync.aligned.m8n8.x4.shared.b16 {%0,%1,%2,%3}, [%4];"
                 : "=r"(r[0]), "=r"(r[1]), "=r"(r[2]), "=r"(r[3]) : "r"(addr));
}
__device__ __forceinline__ void ldsm_x4t(uint32_t* r, uint32_t addr) {
    asm volatile("ldmatrix.sync.aligned.m8n8.x4.trans.shared.b16 {%0,%1,%2,%3}, [%4];"
                 : "=r"(r[0]), "=r"(r[1]), "=r"(r[2]), "=r"(r[3]) : "r"(addr));
}
__device__ __forceinline__ void ldsm_x2t(uint32_t* r, uint32_t addr) {
    asm volatile("ldmatrix.sync.aligned.m8n8.x2.trans.shared.b16 {%0,%1}, [%2];"
                 : "=r"(r[0]), "=r"(r[1]) : "r"(addr));
}
__device__ __forceinline__ void mma16816(float* d, const uint32_t* a, uint32_t b0, uint32_t b1) {
    asm volatile(
        "mma.sync.aligned.m16n8k16.row.col.f32.f16.f16.f32 "
        "{%0,%1,%2,%3}, {%4,%5,%6,%7}, {%8,%9}, {%0,%1,%2,%3};"
        : "+f"(d[0]), "+f"(d[1]), "+f"(d[2]), "+f"(d[3])
        : "r"(a[0]), "r"(a[1]), "r"(a[2]), "r"(a[3]), "r"(b0), "r"(b1));
}

// ------------------------- edge aggregation kernels -------------------------
__global__ void detect_kernel(const int* __restrict__ ei32) {
    if (blockIdx.x == 0 && threadIdx.x == 0) {
        int orv = 0;
        for (int i = 1; i < 128; i += 2) orv |= ei32[i];
        g_is64 = (orv == 0) ? 1 : 0;
    }
}
__device__ __forceinline__ int load_idx(const void* ei, long long pos, int is64) {
    if (is64) return (int)((const long long*)ei)[pos];
    return ((const int*)ei)[pos];
}
__global__ void zero_deg_kernel() {
    int i = blockIdx.x * blockDim.x + threadIdx.x;
    if (i < NN) g_deg[i] = 0.0f;
}
__global__ void deg_kernel(const void* __restrict__ ei) {
    const int is64 = g_is64;
    long long stride = (long long)gridDim.x * blockDim.x;
    for (long long e = (long long)blockIdx.x * blockDim.x + threadIdx.x; e < EE; e += stride) {
        int d = load_idx(ei, (long long)EE + e, is64);
        atomicAdd(&g_deg[d], 1.0f);
    }
}
__global__ void inv_init_kernel(const float* __restrict__ x) {
    int i = blockIdx.x * blockDim.x + threadIdx.x;
    if (i < NN) {
        float inv = rsqrtf(g_deg[i] + 1.0f);
        g_inv[i] = inv;
        g_agg[i] = x[i] * inv * inv;
    }
}
__global__ void edge_agg_kernel(const float* __restrict__ x, const void* __restrict__ ei) {
    const int is64 = g_is64;
    long long stride = (long long)gridDim.x * blockDim.x;
    for (long long e = (long long)blockIdx.x * blockDim.x + threadIdx.x; e < EE; e += stride) {
        int s = load_idx(ei, e, is64);
        int d = load_idx(ei, (long long)EE + e, is64);
        atomicAdd(&g_agg[d], x[s] * g_inv[s] * g_inv[d]);
    }
}

// ------------------- weight prep: fp32 -> single fp16 plane -----------------
__global__ void prep_w_kernel(Params p) {
    int idx = blockIdx.x * blockDim.x + threadIdx.x;
    const int total = 6 * NCHK * 32 * BNC;
    if (idx >= total) return;
    int n = idx % BNC;
    int k = (idx / BNC) % 32;
    int c = (idx / (BNC * 32)) % NCHK;
    int l = idx / (BNC * 32 * NCHK);
    int kg = c * 32 + k;
    float v = 0.0f;
    if (kg < HID && n < HID) v = p.W[l + 1][kg * HID + n];
    g_wtH[l][c][k][n] = __float2half_rn(v);
}

// ------------------------------ fused MLP kernel ----------------------------
__device__ __forceinline__ void a_store(char* sm, int r, int j, float v0, float v1) {
    __half h0 = __float2half_rn(v0), h1 = __float2half_rn(v1);
    uint32_t hp = (uint32_t)__half_as_ushort(h0) | ((uint32_t)__half_as_ushort(h1) << 16);
    *(uint32_t*)(sm + SM_A + r * (CAC * 2) + j * 2) = hp;
}

__global__ void __launch_bounds__(THREADS, 1) mlp_kernel(Params p, float* __restrict__ out) {
    extern __shared__ char sm[];
    const uint32_t sbase = smem_u32(sm);
    const int tid  = threadIdx.x;
    const int wid  = tid >> 5;
    const int lane = tid & 31;
    const int wr   = wid & 3;       // row group: rows 32*wr..+31 (two m16 subtiles)
    const int wc   = wid >> 2;      // col half: cols 104*wc..+103
    const int row0 = blockIdx.x * MT;

    // ldmatrix lane address components
    const int mrow  = (lane & 7) + 8 * ((lane >> 3) & 1);
    const int koff8 = 8 * (lane >> 4);
    const uint32_t aP0 = sbase + SM_A + (wr * 32 + mrow) * (CAC * 2) + koff8 * 2;
    const uint32_t aP1 = aP0 + 16 * (CAC * 2);
    const uint32_t bOff = (uint32_t)(mrow * (BNC * 2) + koff8 * 2);

    const char* wflat = (const char*)&g_wtH[0][0][0][0];

    // stage global chunk 0 into buffer 0 (overlaps with layer-0 gather below)
    for (int i = tid * 16; i < BUFSZ; i += THREADS * 16)
        cp16(sbase + SM_B + i, wflat + i);
    CP_COMMIT();

    // ---- layer 0: A = relu(agg * W0 + b0) -> fp16, zero padding ----
    {
        const float* W0 = p.W[0];
        const float* b0 = p.b[0];
        for (int idx = tid; idx < MT * (CAC / 2); idx += THREADS) {
            int r = idx / (CAC / 2);
            int j = (idx - r * (CAC / 2)) * 2;
            float agg = g_agg[row0 + r];
            float v0 = (j < HID)     ? fmaxf(fmaf(agg, W0[j],     b0[j]),     0.0f) : 0.0f;
            float v1 = (j + 1 < HID) ? fmaxf(fmaf(agg, W0[j + 1], b0[j + 1]), 0.0f) : 0.0f;
            a_store(sm, r, j, v0, v1);
        }
    }
    __syncthreads();

    for (int l = 1; l <= 6; ++l) {
        float acc[2][13][4];
        #pragma unroll
        for (int s = 0; s < 2; ++s)
            #pragma unroll
            for (int t = 0; t < 13; ++t)
                #pragma unroll
                for (int q = 0; q < 4; ++q) acc[s][t][q] = 0.0f;
        float acc12[4] = {0.0f, 0.0f, 0.0f, 0.0f};   // tile 12 (rows subtile = wc)

        for (int c = 0; c < NCHK; ++c) {
            const int g = (l - 1) * NCHK + c;           // global chunk id
            const uint32_t curB = sbase + SM_B + (g & 1) * BUFSZ;
            if (g + 1 < NG) {
                // stage chunk g+1 (possibly next layer's chunk 0) into other buffer
                const char* src = wflat + (size_t)(g + 1) * BUFSZ;
                uint32_t dst = sbase + SM_B + ((g + 1) & 1) * BUFSZ;
                for (int i = tid * 16; i < BUFSZ; i += THREADS * 16)
                    cp16(dst + i, src + i);
                CP_COMMIT();
                CP_WAIT1();       // chunk g fully arrived
            } else {
                CP_WAIT0();
            }
            __syncthreads();      // chunk g visible to all warps

            #pragma unroll
            for (int ks = 0; ks < 2; ++ks) {
                const int kb = c * 32 + ks * 16;
                uint32_t a0[4], a1[4];
                ldsm_x4(a0, aP0 + kb * 2);
                ldsm_x4(a1, aP1 + kb * 2);
                const uint32_t bk = curB + bOff + ks * 16 * (BNC * 2);
                #pragma unroll
                for (int pr = 0; pr < 6; ++pr) {
                    const int nc = wc * 104 + pr * 16;
                    uint32_t bh[4];
                    ldsm_x4t(bh, bk + nc * 2);
                    mma16816(acc[0][2 * pr],     a0, bh[0], bh[1]);
                    mma16816(acc[0][2 * pr + 1], a0, bh[2], bh[3]);
                    mma16816(acc[1][2 * pr],     a1, bh[0], bh[1]);
                    mma16816(acc[1][2 * pr + 1], a1, bh[2], bh[3]);
                }
                // tile 12 (global cols 96..103): wc0 -> row subtile 0, wc1 -> subtile 1.
                {
                    uint32_t bh2[2];
                    ldsm_x2t(bh2, bk + 96 * 2);
                    if (wc == 0) {
                        mma16816(acc12, a0, bh2[0], bh2[1]);
                    } else {
                        mma16816(acc12, a1, bh2[0], bh2[1]);
                    }
                }
            }
            __syncthreads();   // all reads of curB done before it is restaged
        }

        if (l < 6) {
            // epilogue: bias + relu + fp16 back into A
            const float* bias = p.b[l];
            #pragma unroll
            for (int s = 0; s < 2; ++s) {
                const int r0 = wr * 32 + s * 16 + (lane >> 2);
                const int r1 = r0 + 8;
                #pragma unroll
                for (int t = 0; t < 12; ++t) {   // j, j+1 always < 200
                    int j = wc * 104 + t * 8 + 2 * (lane & 3);
                    float bj0 = bias[j], bj1 = bias[j + 1];
                    a_store(sm, r0, j, fmaxf(acc[s][t][0] + bj0, 0.0f),
                                       fmaxf(acc[s][t][1] + bj1, 0.0f));
                    a_store(sm, r1, j, fmaxf(acc[s][t][2] + bj0, 0.0f),
                                       fmaxf(acc[s][t][3] + bj1, 0.0f));
                }
            }
            {   // tile 12: rows of subtile s = wc, global cols 96..103
                const int r0 = wr * 32 + wc * 16 + (lane >> 2);
                const int r1 = r0 + 8;
                int j = 96 + 2 * (lane & 3);
                float bj0 = bias[j], bj1 = bias[j + 1];
                a_store(sm, r0, j, fmaxf(acc12[0] + bj0, 0.0f),
                                   fmaxf(acc12[1] + bj1, 0.0f));
                a_store(sm, r1, j, fmaxf(acc12[2] + bj0, 0.0f),
                                   fmaxf(acc12[3] + bj1, 0.0f));
            }
            __syncthreads();   // A ready for next layer's ldmatrix
        } else {
            // final: relu(acc + b6) dot W7 -> reduce -> sigmoid
            const float* bias = p.b[6];
            const float* W7   = p.W[7];
            float* red = (float*)(sm + SM_B);
            #pragma unroll
            for (int s = 0; s < 2; ++s) {
                const int r0 = wr * 32 + s * 16 + (lane >> 2);
                const int r1 = r0 + 8;
                float p0 = 0.0f, p1 = 0.0f;
                #pragma unroll
                for (int t = 0; t < 12; ++t) {
                    int j = wc * 104 + t * 8 + 2 * (lane & 3);
                    float bj0 = bias[j], w0 = W7[j];
                    float bj1 = bias[j + 1], w1 = W7[j + 1];
                    p0 = fmaf(fmaxf(acc[s][t][0] + bj0, 0.0f), w0, p0);
                    p0 = fmaf(fmaxf(acc[s][t][1] + bj1, 0.0f), w1, p0);
                    p1 = fmaf(fmaxf(acc[s][t][2] + bj0, 0.0f), w0, p1);
                    p1 = fmaf(fmaxf(acc[s][t][3] + bj1, 0.0f), w1, p1);
                }
                if (s == wc) {   // tile 12 contribution (static acc12)
                    int j = 96 + 2 * (lane & 3);
                    float bj0 = bias[j], w0 = W7[j];
                    float bj1 = bias[j + 1], w1 = W7[j + 1];
                    p0 = fmaf(fmaxf(acc12[0] + bj0, 0.0f), w0, p0);
                    p0 = fmaf(fmaxf(acc12[1] + bj1, 0.0f), w1, p0);
                    p1 = fmaf(fmaxf(acc12[2] + bj0, 0.0f), w0, p1);
                    p1 = fmaf(fmaxf(acc12[3] + bj1, 0.0f), w1, p1);
                }
                p0 += __shfl_xor_sync(0xffffffff, p0, 1);
                p0 += __shfl_xor_sync(0xffffffff, p0, 2);
                p1 += __shfl_xor_sync(0xffffffff, p1, 1);
                p1 += __shfl_xor_sync(0xffffffff, p1, 2);
                if ((lane & 3) == 0) {
                    red[r0 * 2 + wc] = p0;
                    red[r1 * 2 + wc] = p1;
                }
            }
            __syncthreads();
            if (tid < MT) {
                float s = red[tid * 2] + red[tid * 2 + 1] + p.b[7][0];
                out[row0 + tid] = 1.0f / (1.0f + expf(-s));
            }
        }
    }
}

// ---------------------------------------------------------------------------
extern "C" void kernel_launch(void* const* d_in, const int* in_sizes, int n_in,
                              void* d_out, int out_size) {
    const float* x  = (const float*)d_in[0];
    const void*  ei = d_in[1];
    Params p;
    for (int i = 0; i < 8; ++i) {
        p.W[i] = (const float*)d_in[2 + 2 * i];
        p.b[i] = (const float*)d_in[3 + 2 * i];
    }
    float* out = (float*)d_out;

    cudaFuncSetAttribute(mlp_kernel, cudaFuncAttributeMaxDynamicSharedMemorySize, SMEM_BYTES);

    detect_kernel<<<1, 32>>>((const int*)ei);
    prep_w_kernel<<<(6 * NCHK * 32 * BNC + 255) / 256, 256>>>(p);
    zero_deg_kernel<<<NN / 256, 256>>>();
    deg_kernel<<<2048, 256>>>(ei);
    inv_init_kernel<<<NN / 256, 256>>>(x);
    edge_agg_kernel<<<2048, 256>>>(x, ei);
    mlp_kernel<<<NN / MT, THREADS, SMEM_BYTES>>>(p, out);
}

// round 14
// speedup vs baseline: 8.0793x; 1.0547x over previous
#include <cuda_runtime.h>
#include <cuda_fp16.h>
#include <math.h>
#include <stdint.h>

#define NN   262144
#define EE   2097152
#define HID  200
#define MT   128                 // rows per CTA
#define CAC  232                 // A smem cols (k padded; stride 464B conflict-free)
#define NCHK 7                   // k chunks of 32 (224 >= 200, zero padded)
#define NG   (6 * NCHK)          // 42 global chunks across layers 1..6
#define BNC  216                 // B smem cols (n padded; stride 432B conflict-free)
#define SA_PLANE (MT * CAC * 2)          // 59392 B (single fp16 A plane)
#define SM_A     0
#define SM_B     SA_PLANE
#define BUFSZ    (32 * BNC * 2)          // 13824 B (single fp16 B plane)
#define NBUF     4                       // ring of 4 B buffers, prefetch depth 2
#define SMEM_BYTES (SM_B + NBUF * BUFSZ) // 114688
#define THREADS  256

// ------------------------- device globals (scratch) -------------------------
__device__ float g_deg[NN];
__device__ float g_inv[NN];
__device__ float g_agg[NN];
__device__ int   g_is64;
// weights as single fp16 plane: [layer 1..6][chunk][k32][BNC]
__device__ __align__(16) __half g_wtH[6][NCHK][32][BNC];

struct Params {
    const float* W[8];
    const float* b[8];
};

// ------------------------------- PTX helpers --------------------------------
__device__ __forceinline__ uint32_t smem_u32(const void* p) {
    uint32_t a;
    asm("{ .reg .u64 t; cvta.to.shared.u64 t, %1; cvt.u32.u64 %0, t; }" : "=r"(a) : "l"(p));
    return a;
}
__device__ __forceinline__ void cp16(uint32_t sdst, const void* gsrc) {
    asm volatile("cp.async.cg.shared.global [%0], [%1], 16;" :: "r"(sdst), "l"(gsrc));
}
#define CP_COMMIT() asm volatile("cp.async.commit_group;")
#define CP_WAIT1()  asm volatile("cp.async.wait_group 1;")
#define CP_WAIT0()  asm volatile("cp.async.wait_group 0;")

__device__ __forceinline__ void ldsm_x4(uint32_t* r, uint32_t addr) {
    asm volatile("ldmatrix.sync.aligned.m8n8.x4.shared.b16 {%0,%1,%2,%3}, [%4];"
                 : "=r"(r[0]), "=r"(r[1]), "=r"(r[2]), "=r"(r[3]) : "r"(addr));
}
__device__ __forceinline__ void ldsm_x4t(uint32_t* r, uint32_t addr) {
    asm volatile("ldmatrix.sync.aligned.m8n8.x4.trans.shared.b16 {%0,%1,%2,%3}, [%4];"
                 : "=r"(r[0]), "=r"(r[1]), "=r"(r[2]), "=r"(r[3]) : "r"(addr));
}
__device__ __forceinline__ void ldsm_x2t(uint32_t* r, uint32_t addr) {
    asm volatile("ldmatrix.sync.aligned.m8n8.x2.trans.shared.b16 {%0,%1}, [%2];"
                 : "=r"(r[0]), "=r"(r[1]) : "r"(addr));
}
__device__ __forceinline__ void mma16816(float* d, const uint32_t* a, uint32_t b0, uint32_t b1) {
    asm volatile(
        "mma.sync.aligned.m16n8k16.row.col.f32.f16.f16.f32 "
        "{%0,%1,%2,%3}, {%4,%5,%6,%7}, {%8,%9}, {%0,%1,%2,%3};"
        : "+f"(d[0]), "+f"(d[1]), "+f"(d[2]), "+f"(d[3])
        : "r"(a[0]), "r"(a[1]), "r"(a[2]), "r"(a[3]), "r"(b0), "r"(b1));
}

// ------------------------- edge aggregation kernels -------------------------
__global__ void detect_kernel(const int* __restrict__ ei32) {
    if (blockIdx.x == 0 && threadIdx.x == 0) {
        int orv = 0;
        for (int i = 1; i < 128; i += 2) orv |= ei32[i];
        g_is64 = (orv == 0) ? 1 : 0;
    }
}
__device__ __forceinline__ int load_idx(const void* ei, long long pos, int is64) {
    if (is64) return (int)((const long long*)ei)[pos];
    return ((const int*)ei)[pos];
}
__global__ void zero_deg_kernel() {
    int i = blockIdx.x * blockDim.x + threadIdx.x;
    if (i < NN) g_deg[i] = 0.0f;
}
__global__ void deg_kernel(const void* __restrict__ ei) {
    const int is64 = g_is64;
    long long stride = (long long)gridDim.x * blockDim.x;
    for (long long e = (long long)blockIdx.x * blockDim.x + threadIdx.x; e < EE; e += stride) {
        int d = load_idx(ei, (long long)EE + e, is64);
        atomicAdd(&g_deg[d], 1.0f);
    }
}
__global__ void inv_init_kernel(const float* __restrict__ x) {
    int i = blockIdx.x * blockDim.x + threadIdx.x;
    if (i < NN) {
        float inv = rsqrtf(g_deg[i] + 1.0f);
        g_inv[i] = inv;
        g_agg[i] = x[i] * inv * inv;
    }
}
__global__ void edge_agg_kernel(const float* __restrict__ x, const void* __restrict__ ei) {
    const int is64 = g_is64;
    long long stride = (long long)gridDim.x * blockDim.x;
    for (long long e = (long long)blockIdx.x * blockDim.x + threadIdx.x; e < EE; e += stride) {
        int s = load_idx(ei, e, is64);
        int d = load_idx(ei, (long long)EE + e, is64);
        atomicAdd(&g_agg[d], x[s] * g_inv[s] * g_inv[d]);
    }
}

// ------------------- weight prep: fp32 -> single fp16 plane -----------------
__global__ void prep_w_kernel(Params p) {
    int idx = blockIdx.x * blockDim.x + threadIdx.x;
    const int total = 6 * NCHK * 32 * BNC;
    if (idx >= total) return;
    int n = idx % BNC;
    int k = (idx / BNC) % 32;
    int c = (idx / (BNC * 32)) % NCHK;
    int l = idx / (BNC * 32 * NCHK);
    int kg = c * 32 + k;
    float v = 0.0f;
    if (kg < HID && n < HID) v = p.W[l + 1][kg * HID + n];
    g_wtH[l][c][k][n] = __float2half_rn(v);
}

// ------------------------------ fused MLP kernel ----------------------------
__device__ __forceinline__ void a_store(char* sm, int r, int j, float v0, float v1) {
    __half h0 = __float2half_rn(v0), h1 = __float2half_rn(v1);
    uint32_t hp = (uint32_t)__half_as_ushort(h0) | ((uint32_t)__half_as_ushort(h1) << 16);
    *(uint32_t*)(sm + SM_A + r * (CAC * 2) + j * 2) = hp;
}

__global__ void __launch_bounds__(THREADS, 1) mlp_kernel(Params p, float* __restrict__ out) {
    extern __shared__ char sm[];
    const uint32_t sbase = smem_u32(sm);
    const int tid  = threadIdx.x;
    const int wid  = tid >> 5;
    const int lane = tid & 31;
    const int wr   = wid & 3;       // row group: rows 32*wr..+31 (two m16 subtiles)
    const int wc   = wid >> 2;      // col half: cols 104*wc..+103
    const int row0 = blockIdx.x * MT;

    // ldmatrix lane address components
    const int mrow  = (lane & 7) + 8 * ((lane >> 3) & 1);
    const int koff8 = 8 * (lane >> 4);
    const uint32_t aP0 = sbase + SM_A + (wr * 32 + mrow) * (CAC * 2) + koff8 * 2;
    const uint32_t aP1 = aP0 + 16 * (CAC * 2);
    const uint32_t bOff = (uint32_t)(mrow * (BNC * 2) + koff8 * 2);

    const char* wflat = (const char*)&g_wtH[0][0][0][0];

    // stage chunks 0 and 1 into ring slots 0,1 (overlaps layer-0 gather)
    for (int i = tid * 16; i < BUFSZ; i += THREADS * 16)
        cp16(sbase + SM_B + i, wflat + i);
    CP_COMMIT();
    for (int i = tid * 16; i < BUFSZ; i += THREADS * 16)
        cp16(sbase + SM_B + BUFSZ + i, wflat + BUFSZ + i);
    CP_COMMIT();

    // ---- layer 0: A = relu(agg * W0 + b0) -> fp16, zero padding ----
    {
        const float* W0 = p.W[0];
        const float* b0 = p.b[0];
        for (int idx = tid; idx < MT * (CAC / 2); idx += THREADS) {
            int r = idx / (CAC / 2);
            int j = (idx - r * (CAC / 2)) * 2;
            float agg = g_agg[row0 + r];
            float v0 = (j < HID)     ? fmaxf(fmaf(agg, W0[j],     b0[j]),     0.0f) : 0.0f;
            float v1 = (j + 1 < HID) ? fmaxf(fmaf(agg, W0[j + 1], b0[j + 1]), 0.0f) : 0.0f;
            a_store(sm, r, j, v0, v1);
        }
    }
    __syncthreads();   // cross-warp A writes of layer 0

    for (int l = 1; l <= 6; ++l) {
        float acc[2][13][4];
        #pragma unroll
        for (int s = 0; s < 2; ++s)
            #pragma unroll
            for (int t = 0; t < 13; ++t)
                #pragma unroll
                for (int q = 0; q < 4; ++q) acc[s][t][q] = 0.0f;
        float acc12[4] = {0.0f, 0.0f, 0.0f, 0.0f};   // tile 12 (rows subtile = wc)

        for (int c = 0; c < NCHK; ++c) {
            const int g = (l - 1) * NCHK + c;           // global chunk id
            // wait for chunk g (committed 2 iterations ago; <=1 pending after)
            if (g < NG - 1) { CP_WAIT1(); } else { CP_WAIT0(); }
            __syncthreads();   // chunk g visible; all reads of slot (g+2)&3 done

            if (g + 2 < NG) {  // stage chunk g+2 into ring slot (g+2)&3
                const char* src = wflat + (size_t)(g + 2) * BUFSZ;
                uint32_t dst = sbase + SM_B + ((g + 2) & (NBUF - 1)) * BUFSZ;
                for (int i = tid * 16; i < BUFSZ; i += THREADS * 16)
                    cp16(dst + i, src + i);
                CP_COMMIT();
            }

            const uint32_t curB = sbase + SM_B + (g & (NBUF - 1)) * BUFSZ;
            #pragma unroll
            for (int ks = 0; ks < 2; ++ks) {
                const int kb = c * 32 + ks * 16;
                uint32_t a0[4], a1[4];
                ldsm_x4(a0, aP0 + kb * 2);
                ldsm_x4(a1, aP1 + kb * 2);
                const uint32_t bk = curB + bOff + ks * 16 * (BNC * 2);
                #pragma unroll
                for (int pr = 0; pr < 6; ++pr) {
                    const int nc = wc * 104 + pr * 16;
                    uint32_t bh[4];
                    ldsm_x4t(bh, bk + nc * 2);
                    mma16816(acc[0][2 * pr],     a0, bh[0], bh[1]);
                    mma16816(acc[0][2 * pr + 1], a0, bh[2], bh[3]);
                    mma16816(acc[1][2 * pr],     a1, bh[0], bh[1]);
                    mma16816(acc[1][2 * pr + 1], a1, bh[2], bh[3]);
                }
                // tile 12 (global cols 96..103): wc0 -> row subtile 0, wc1 -> subtile 1.
                {
                    uint32_t bh2[2];
                    ldsm_x2t(bh2, bk + 96 * 2);
                    if (wc == 0) {
                        mma16816(acc12, a0, bh2[0], bh2[1]);
                    } else {
                        mma16816(acc12, a1, bh2[0], bh2[1]);
                    }
                }
            }
            // no trailing barrier: next chunk's barrier orders buffer reuse;
            // A rows are private per warp (each warp reads/writes only its own).
        }

        if (l < 6) {
            // epilogue: bias + relu + fp16 back into A (own rows only, no barrier)
            const float* bias = p.b[l];
            #pragma unroll
            for (int s = 0; s < 2; ++s) {
                const int r0 = wr * 32 + s * 16 + (lane >> 2);
                const int r1 = r0 + 8;
                #pragma unroll
                for (int t = 0; t < 12; ++t) {   // j, j+1 always < 200
                    int j = wc * 104 + t * 8 + 2 * (lane & 3);
                    float bj0 = bias[j], bj1 = bias[j + 1];
                    a_store(sm, r0, j, fmaxf(acc[s][t][0] + bj0, 0.0f),
                                       fmaxf(acc[s][t][1] + bj1, 0.0f));
                    a_store(sm, r1, j, fmaxf(acc[s][t][2] + bj0, 0.0f),
                                       fmaxf(acc[s][t][3] + bj1, 0.0f));
                }
            }
            {   // tile 12: rows of subtile s = wc, global cols 96..103
                const int r0 = wr * 32 + wc * 16 + (lane >> 2);
                const int r1 = r0 + 8;
                int j = 96 + 2 * (lane & 3);
                float bj0 = bias[j], bj1 = bias[j + 1];
                a_store(sm, r0, j, fmaxf(acc12[0] + bj0, 0.0f),
                                   fmaxf(acc12[1] + bj1, 0.0f));
                a_store(sm, r1, j, fmaxf(acc12[2] + bj0, 0.0f),
                                   fmaxf(acc12[3] + bj1, 0.0f));
            }
            // NOTE: warp's A-row writes are only consumed by the same warp's
            // ldmatrix next layer -> no barrier needed here. Chunk barrier at
            // the top of the next layer's first iteration publishes B.
        } else {
            // final: relu(acc + b6) dot W7 -> reduce -> sigmoid
            const float* bias = p.b[6];
            const float* W7   = p.W[7];
            float* red = (float*)(sm + SM_B);   // <= 1KB, inside drained slot 0
            #pragma unroll
            for (int s = 0; s < 2; ++s) {
                const int r0 = wr * 32 + s * 16 + (lane >> 2);
                const int r1 = r0 + 8;
                float p0 = 0.0f, p1 = 0.0f;
                #pragma unroll
                for (int t = 0; t < 12; ++t) {
                    int j = wc * 104 + t * 8 + 2 * (lane & 3);
                    float bj0 = bias[j], w0 = W7[j];
                    float bj1 = bias[j + 1], w1 = W7[j + 1];
                    p0 = fmaf(fmaxf(acc[s][t][0] + bj0, 0.0f), w0, p0);
                    p0 = fmaf(fmaxf(acc[s][t][1] + bj1, 0.0f), w1, p0);
                    p1 = fmaf(fmaxf(acc[s][t][2] + bj0, 0.0f), w0, p1);
                    p1 = fmaf(fmaxf(acc[s][t][3] + bj1, 0.0f), w1, p1);
                }
                if (s == wc) {   // tile 12 contribution (static acc12)
                    int j = 96 + 2 * (lane & 3);
                    float bj0 = bias[j], w0 = W7[j];
                    float bj1 = bias[j + 1], w1 = W7[j + 1];
                    p0 = fmaf(fmaxf(acc12[0] + bj0, 0.0f), w0, p0);
                    p0 = fmaf(fmaxf(acc12[1] + bj1, 0.0f), w1, p0);
                    p1 = fmaf(fmaxf(acc12[2] + bj0, 0.0f), w0, p1);
                    p1 = fmaf(fmaxf(acc12[3] + bj1, 0.0f), w1, p1);
                }
                p0 += __shfl_xor_sync(0xffffffff, p0, 1);
                p0 += __shfl_xor_sync(0xffffffff, p0, 2);
                p1 += __shfl_xor_sync(0xffffffff, p1, 1);
                p1 += __shfl_xor_sync(0xffffffff, p1, 2);
                if ((lane & 3) == 0) {
                    red[r0 * 2 + wc] = p0;
                    red[r1 * 2 + wc] = p1;
                }
            }
            __syncthreads();
            if (tid < MT) {
                float s = red[tid * 2] + red[tid * 2 + 1] + p.b[7][0];
                out[row0 + tid] = 1.0f / (1.0f + expf(-s));
            }
        }
    }
}

// ---------------------------------------------------------------------------
extern "C" void kernel_launch(void* const* d_in, const int* in_sizes, int n_in,
                              void* d_out, int out_size) {
    const float* x  = (const float*)d_in[0];
    const void*  ei = d_in[1];
    Params p;
    for (int i = 0; i < 8; ++i) {
        p.W[i] = (const float*)d_in[2 + 2 * i];
        p.b[i] = (const float*)d_in[3 + 2 * i];
    }
    float* out = (float*)d_out;

    cudaFuncSetAttribute(mlp_kernel, cudaFuncAttributeMaxDynamicSharedMemorySize, SMEM_BYTES);

    detect_kernel<<<1, 32>>>((const int*)ei);
    prep_w_kernel<<<(6 * NCHK * 32 * BNC + 255) / 256, 256>>>(p);
    zero_deg_kernel<<<NN / 256, 256>>>();
    deg_kernel<<<2048, 256>>>(ei);
    inv_init_kernel<<<NN / 256, 256>>>(x);
    edge_agg_kernel<<<2048, 256>>>(x, ei);
    mlp_kernel<<<NN / MT, THREADS, SMEM_BYTES>>>(p, out);
}